// round 1
// baseline (speedup 1.0000x reference)
#include <cuda_runtime.h>

#define D   1024
#define SEQ 2048
#define BAT 2
#define H   16
#define HD  64
#define TOK (BAT * SEQ)   // 4096

// ---------------- scratch (no allocations allowed) ----------------
__device__ float g_q[TOK * D];
__device__ float g_k[TOK * D];
__device__ float g_v[TOK * D];
__device__ float g_ctx[TOK * D];
__device__ float g_att[TOK * D];

// ---------------- fast exp on FMA pipe (avoid MUFU bottleneck) ----------------
// exp(x) for x <= 0. Degree-5 Taylor of 2^f, rel err ~1.5e-4.
__device__ __forceinline__ float fexp(float x) {
    float t = fmaxf(x * 1.4426950408889634f, -125.0f);
    float fi = floorf(t);
    float f  = t - fi;
    float r  = 0.0013333558f;
    r = r * f + 0.0096181291f;
    r = r * f + 0.0555041086f;
    r = r * f + 0.2402265069f;
    r = r * f + 0.6931471806f;
    r = r * f + 1.0f;
    int e = (int)fi;
    return __int_as_float((e + 127) << 23) * r;
}

// ---------------- GEMM: C[4096,1024] = A[4096,1024] @ W[1024,1024]^T + bias ----------------
// BM=BN=128, BK=16, 256 threads, 8x8 per-thread microtile (split 4+4 with 64 offset).
__global__ void __launch_bounds__(256) gemm_bias_kernel(
    const float* __restrict__ A, const float* __restrict__ W,
    const float* __restrict__ bias, float* __restrict__ C)
{
    __shared__ __align__(16) float As[16][128];
    __shared__ __align__(16) float Bs[16][128];

    const int tid  = threadIdx.x;
    const int bm   = blockIdx.y * 128;
    const int bn   = blockIdx.x * 128;
    const int trow = (tid >> 4) * 4;   // 0..60
    const int tcol = (tid & 15) * 4;   // 0..60
    const int lr   = tid >> 1;         // 0..127 (load row)

    float acc[8][8];
#pragma unroll
    for (int i = 0; i < 8; i++)
#pragma unroll
        for (int j = 0; j < 8; j++) acc[i][j] = 0.0f;

    for (int k0 = 0; k0 < 1024; k0 += 16) {
#pragma unroll
        for (int i = 0; i < 2; i++) {
            const int c4 = ((tid & 1) * 2 + i) * 4;   // 0,4,8,12
            float4 av = *(const float4*)(A + (size_t)(bm + lr) * 1024 + k0 + c4);
            As[c4 + 0][lr] = av.x; As[c4 + 1][lr] = av.y;
            As[c4 + 2][lr] = av.z; As[c4 + 3][lr] = av.w;
            float4 wv = *(const float4*)(W + (size_t)(bn + lr) * 1024 + k0 + c4);
            Bs[c4 + 0][lr] = wv.x; Bs[c4 + 1][lr] = wv.y;
            Bs[c4 + 2][lr] = wv.z; Bs[c4 + 3][lr] = wv.w;
        }
        __syncthreads();
#pragma unroll
        for (int kk = 0; kk < 16; kk++) {
            float4 a0 = *(const float4*)&As[kk][trow];
            float4 a1 = *(const float4*)&As[kk][trow + 64];
            float4 b0 = *(const float4*)&Bs[kk][tcol];
            float4 b1 = *(const float4*)&Bs[kk][tcol + 64];
            float a[8] = {a0.x, a0.y, a0.z, a0.w, a1.x, a1.y, a1.z, a1.w};
            float b[8] = {b0.x, b0.y, b0.z, b0.w, b1.x, b1.y, b1.z, b1.w};
#pragma unroll
            for (int i = 0; i < 8; i++)
#pragma unroll
                for (int j = 0; j < 8; j++) acc[i][j] += a[i] * b[j];
        }
        __syncthreads();
    }

    float bia0[4], bia1[4];
#pragma unroll
    for (int j = 0; j < 4; j++) {
        bia0[j] = bias[bn + tcol + j];
        bia1[j] = bias[bn + tcol + 64 + j];
    }
#pragma unroll
    for (int i = 0; i < 8; i++) {
        const int r = bm + trow + ((i < 4) ? i : (60 + i));
        float4 o0, o1;
        o0.x = acc[i][0] + bia0[0]; o0.y = acc[i][1] + bia0[1];
        o0.z = acc[i][2] + bia0[2]; o0.w = acc[i][3] + bia0[3];
        o1.x = acc[i][4] + bia1[0]; o1.y = acc[i][5] + bia1[1];
        o1.z = acc[i][6] + bia1[2]; o1.w = acc[i][7] + bia1[3];
        *(float4*)(C + (size_t)r * 1024 + bn + tcol)      = o0;
        *(float4*)(C + (size_t)r * 1024 + bn + tcol + 64) = o1;
    }
}

// ---------------- Flash attention (fp32, online softmax, poly exp) ----------------
// Block: 128 q-rows, one (b,h). K/V tiles of 64 rows in smem.
__global__ void __launch_bounds__(128) attn_kernel(
    const float* __restrict__ Q, const float* __restrict__ K,
    const float* __restrict__ V, float* __restrict__ O)
{
    __shared__ __align__(16) float Ks[64][64];
    __shared__ __align__(16) float Vs[64][64];

    const int tid = threadIdx.x;
    const int h   = blockIdx.y;
    const int b   = blockIdx.z;
    const int row = blockIdx.x * 128 + tid;
    const size_t base = (size_t)b * SEQ * D + (size_t)h * HD;

    float q[64], o[64];
#pragma unroll
    for (int d4 = 0; d4 < 16; d4++) {
        float4 t = *(const float4*)(Q + base + (size_t)row * D + d4 * 4);
        q[4 * d4 + 0] = t.x * 0.125f;  // fold 1/sqrt(64) into q
        q[4 * d4 + 1] = t.y * 0.125f;
        q[4 * d4 + 2] = t.z * 0.125f;
        q[4 * d4 + 3] = t.w * 0.125f;
    }
#pragma unroll
    for (int d = 0; d < 64; d++) o[d] = 0.0f;

    float m = -1e30f, l = 0.0f;

    for (int kt = 0; kt < SEQ / 64; kt++) {
        __syncthreads();
#pragma unroll
        for (int i = 0; i < 8; i++) {
            const int f = tid + i * 128;
            const int r = f >> 4;
            const int c = (f & 15) * 4;
            *(float4*)&Ks[r][c] = *(const float4*)(K + base + (size_t)(kt * 64 + r) * D + c);
            *(float4*)&Vs[r][c] = *(const float4*)(V + base + (size_t)(kt * 64 + r) * D + c);
        }
        __syncthreads();

#pragma unroll
        for (int c0 = 0; c0 < 64; c0 += 16) {
            float s[16];
            float cm = m;
#pragma unroll
            for (int jj = 0; jj < 16; jj++) {
                const float4* kr = (const float4*)&Ks[c0 + jj][0];
                float acc = 0.0f;
#pragma unroll
                for (int d4 = 0; d4 < 16; d4++) {
                    float4 kv = kr[d4];
                    acc += q[4 * d4 + 0] * kv.x;
                    acc += q[4 * d4 + 1] * kv.y;
                    acc += q[4 * d4 + 2] * kv.z;
                    acc += q[4 * d4 + 3] * kv.w;
                }
                s[jj] = acc;
                cm = fmaxf(cm, acc);
            }
            const float corr = fexp(m - cm);
            m = cm;
            l *= corr;
#pragma unroll
            for (int d = 0; d < 64; d++) o[d] *= corr;
#pragma unroll
            for (int jj = 0; jj < 16; jj++) {
                const float p = fexp(s[jj] - m);
                l += p;
                const float4* vr = (const float4*)&Vs[c0 + jj][0];
#pragma unroll
                for (int d4 = 0; d4 < 16; d4++) {
                    float4 vv = vr[d4];
                    o[4 * d4 + 0] += p * vv.x;
                    o[4 * d4 + 1] += p * vv.y;
                    o[4 * d4 + 2] += p * vv.z;
                    o[4 * d4 + 3] += p * vv.w;
                }
            }
        }
    }

    const float inv = 1.0f / l;
#pragma unroll
    for (int d4 = 0; d4 < 16; d4++) {
        float4 t;
        t.x = o[4 * d4 + 0] * inv;
        t.y = o[4 * d4 + 1] * inv;
        t.z = o[4 * d4 + 2] * inv;
        t.w = o[4 * d4 + 3] * inv;
        *(float4*)(O + base + (size_t)row * D + d4 * 4) = t;
    }
}

// ---------------- residual + LayerNorm ----------------
__global__ void __launch_bounds__(256) ln_kernel(
    const float* __restrict__ x, const float* __restrict__ y,
    const float* __restrict__ gamma, const float* __restrict__ beta,
    float* __restrict__ out)
{
    __shared__ float red[8];
    const int row = blockIdx.x;
    const int tid = threadIdx.x;

    float4 xv = ((const float4*)(x + (size_t)row * D))[tid];
    float4 yv = ((const float4*)(y + (size_t)row * D))[tid];
    float v[4] = {xv.x + yv.x, xv.y + yv.y, xv.z + yv.z, xv.w + yv.w};

    float s = v[0] + v[1] + v[2] + v[3];
#pragma unroll
    for (int off = 16; off; off >>= 1) s += __shfl_xor_sync(0xffffffffu, s, off);
    if ((tid & 31) == 0) red[tid >> 5] = s;
    __syncthreads();
    if (tid == 0) {
        float t = 0.0f;
        for (int i = 0; i < 8; i++) t += red[i];
        red[0] = t;
    }
    __syncthreads();
    const float mean = red[0] * (1.0f / 1024.0f);
    __syncthreads();

    float ss = 0.0f;
#pragma unroll
    for (int i = 0; i < 4; i++) {
        float d = v[i] - mean;
        ss += d * d;
    }
#pragma unroll
    for (int off = 16; off; off >>= 1) ss += __shfl_xor_sync(0xffffffffu, ss, off);
    if ((tid & 31) == 0) red[tid >> 5] = ss;
    __syncthreads();
    if (tid == 0) {
        float t = 0.0f;
        for (int i = 0; i < 8; i++) t += red[i];
        red[0] = t;
    }
    __syncthreads();
    const float rstd = rsqrtf(red[0] * (1.0f / 1024.0f) + 1e-6f);

    float4 gv = ((const float4*)gamma)[tid];
    float4 bv = ((const float4*)beta)[tid];
    float4 ov;
    ov.x = (v[0] - mean) * rstd * gv.x + bv.x;
    ov.y = (v[1] - mean) * rstd * gv.y + bv.y;
    ov.z = (v[2] - mean) * rstd * gv.z + bv.z;
    ov.w = (v[3] - mean) * rstd * gv.w + bv.w;
    ((float4*)(out + (size_t)row * D))[tid] = ov;
}

// ---------------- launch ----------------
extern "C" void kernel_launch(void* const* d_in, const int* in_sizes, int n_in,
                              void* d_out, int out_size)
{
    const float* x     = (const float*)d_in[0];
    const float* Wq    = (const float*)d_in[1];
    const float* bq    = (const float*)d_in[2];
    const float* Wk    = (const float*)d_in[3];
    const float* bk    = (const float*)d_in[4];
    const float* Wv    = (const float*)d_in[5];
    const float* bv    = (const float*)d_in[6];
    const float* Wo    = (const float*)d_in[7];
    const float* bo    = (const float*)d_in[8];
    const float* gamma = (const float*)d_in[9];
    const float* beta  = (const float*)d_in[10];
    float* out = (float*)d_out;

    float *qp, *kp, *vp, *cp, *ap;
    cudaGetSymbolAddress((void**)&qp, g_q);
    cudaGetSymbolAddress((void**)&kp, g_k);
    cudaGetSymbolAddress((void**)&vp, g_v);
    cudaGetSymbolAddress((void**)&cp, g_ctx);
    cudaGetSymbolAddress((void**)&ap, g_att);

    dim3 gg(8, 32);                 // N/128, M/128
    gemm_bias_kernel<<<gg, 256>>>(x, Wq, bq, qp);
    gemm_bias_kernel<<<gg, 256>>>(x, Wk, bk, kp);
    gemm_bias_kernel<<<gg, 256>>>(x, Wv, bv, vp);
    attn_kernel<<<dim3(16, 16, 2), 128>>>(qp, kp, vp, cp);
    gemm_bias_kernel<<<gg, 256>>>(cp, Wo, bo, ap);
    ln_kernel<<<4096, 256>>>(x, ap, gamma, beta, out);
}

// round 3
// speedup vs baseline: 1.2393x; 1.2393x over previous
#include <cuda_runtime.h>
#include <cstdint>

#define D   1024
#define SEQ 2048
#define BAT 2
#define H   16
#define HD  64
#define TOK (BAT * SEQ)   // 4096

// ---------------- scratch (no allocations allowed) ----------------
__device__ float g_q[TOK * D];
__device__ float g_k[TOK * D];
__device__ float g_v[TOK * D];
__device__ float g_ctx[TOK * D];
__device__ float g_att[TOK * D];

// ==================== helpers ====================
__device__ __forceinline__ uint32_t smem_u32(const void* p) {
    uint32_t a;
    asm("{ .reg .u64 t; cvta.to.shared.u64 t, %1; cvt.u32.u64 %0, t; }" : "=r"(a) : "l"(p));
    return a;
}

__device__ __forceinline__ uint32_t cvt_tf32(float x) {
    uint32_t u;
    asm("cvt.rna.tf32.f32 %0, %1;" : "=r"(u) : "f"(x));
    return u;
}

#define LDSM_X4(r, addr) \
    asm volatile("ldmatrix.sync.aligned.m8n8.x4.shared.b16 {%0,%1,%2,%3}, [%4];" \
                 : "=r"((r)[0]), "=r"((r)[1]), "=r"((r)[2]), "=r"((r)[3]) : "r"(addr))

#define STS128(a0, a1, a2, a3, addr) \
    asm volatile("st.shared.v4.b32 [%0], {%1, %2, %3, %4};" \
                 :: "r"(addr), "r"(a0), "r"(a1), "r"(a2), "r"(a3) : "memory")

#define MMA_TF32(acc, a, b) \
    asm volatile("mma.sync.aligned.m16n8k8.row.col.f32.tf32.tf32.f32 " \
                 "{%0,%1,%2,%3}, {%4,%5,%6,%7}, {%8,%9}, {%0,%1,%2,%3};" \
                 : "+f"((acc)[0]), "+f"((acc)[1]), "+f"((acc)[2]), "+f"((acc)[3]) \
                 : "r"((a)[0]), "r"((a)[1]), "r"((a)[2]), "r"((a)[3]), \
                   "r"((b)[0]), "r"((b)[1]))

// ==================== mma.sync tf32 GEMM ====================
// C[4096,1024] = A[4096,1024] @ W[1024,1024]^T + bias
// BM=BN=128, BK=32, 256 thr, 8 warps (2x4), warp tile 64x32.
// smem: float [2 bufs][A 128x32 | B 128x32], XOR-granule swizzle.
#define BK 32
#define NCHUNK (1024 / BK)
#define GEMM_SMEM (16384 * 4)   // 65536 B

// float index of (row, k) with swizzle: granule g=k>>2 permuted by row&7
__device__ __forceinline__ uint32_t swz_idx(int row, int k) {
    int g = (k >> 2) ^ (row & 7);
    return (uint32_t)((row << 5) + (g << 2) + (k & 3));
}

__global__ void __launch_bounds__(256) gemm_mma(
    const float* __restrict__ A, const float* __restrict__ W,
    const float* __restrict__ bias, float* __restrict__ C)
{
    extern __shared__ float sm[];
    // layout: A0 [0,4096) B0 [4096,8192) A1 [8192,12288) B1 [12288,16384)
    const uint32_t smb = smem_u32(sm);

    const int tid  = threadIdx.x;
    const int lane = tid & 31;
    const int wid  = tid >> 5;
    const int wm   = (wid >> 2) * 64;   // 0 or 64
    const int wn   = (wid & 3) * 32;    // 0,32,64,96
    const int bm   = blockIdx.y * 128;
    const int bn   = blockIdx.x * 128;

    float acc[4][4][4];
#pragma unroll
    for (int mt = 0; mt < 4; mt++)
#pragma unroll
        for (int nt = 0; nt < 4; nt++)
#pragma unroll
            for (int r = 0; r < 4; r++) acc[mt][nt][r] = 0.0f;

    // staging indices: 4 granules per thread per matrix
    int srow[4], sg[4];
#pragma unroll
    for (int i = 0; i < 4; i++) {
        const int lin = tid + i * 256;
        srow[i] = lin >> 3;
        sg[i]   = lin & 7;
    }

    // ---- prologue: stage chunk 0 into buf 0 ----
#pragma unroll
    for (int i = 0; i < 4; i++) {
        const int r = srow[i], g = sg[i];
        float4 av = *(const float4*)(A + (size_t)(bm + r) * 1024 + g * 4);
        STS128(cvt_tf32(av.x), cvt_tf32(av.y), cvt_tf32(av.z), cvt_tf32(av.w),
               smb + 4u * swz_idx(r, g * 4));
        float4 wv = *(const float4*)(W + (size_t)(bn + r) * 1024 + g * 4);
        STS128(cvt_tf32(wv.x), cvt_tf32(wv.y), cvt_tf32(wv.z), cvt_tf32(wv.w),
               smb + 4u * (4096u + swz_idx(r, g * 4)));
    }
    __syncthreads();

    // precompute ldmatrix smem offsets (within a buffer, float units)
    // A: 4 m-tiles
    uint32_t a_off[4], b_off[2];
#pragma unroll
    for (int mt = 0; mt < 4; mt++) {
        const int row = wm + mt * 16 + (lane & 15);
        a_off[mt] = (uint32_t)(row << 5) + (uint32_t)(((lane >> 4) ^ (row & 7)) << 2);
        // (+ kk8*2 granules applied per step via XOR-free add? swizzle is XOR of g
        //  with row&7; g = kk8*2 + half. We must recompute per step.)
    }
    (void)b_off;

    for (int c = 0; c < NCHUNK; c++) {
        const int buf = c & 1;
        const uint32_t a_base = smb + (uint32_t)(buf * 8192) * 4u;
        const uint32_t b_base = a_base + 4096u * 4u;

        // prefetch next chunk from global into registers
        float4 pa[4], pb[4];
        if (c + 1 < NCHUNK) {
            const int k0 = (c + 1) * BK;
#pragma unroll
            for (int i = 0; i < 4; i++) {
                pa[i] = *(const float4*)(A + (size_t)(bm + srow[i]) * 1024 + k0 + sg[i] * 4);
                pb[i] = *(const float4*)(W + (size_t)(bn + srow[i]) * 1024 + k0 + sg[i] * 4);
            }
        }

        // compute: 4 k8 steps
#pragma unroll
        for (int kk8 = 0; kk8 < 4; kk8++) {
            uint32_t af[4][4];
#pragma unroll
            for (int mt = 0; mt < 4; mt++) {
                const int row = wm + mt * 16 + (lane & 15);
                const int g = (kk8 * 2 + (lane >> 4)) ^ (row & 7);
                LDSM_X4(af[mt], a_base + 4u * (uint32_t)((row << 5) + (g << 2)));
            }
            uint32_t bf[2][4];
#pragma unroll
            for (int bt = 0; bt < 2; bt++) {
                const int row = wn + bt * 16 + ((lane >> 4) << 3) + (lane & 7);
                const int g = (kk8 * 2 + ((lane >> 3) & 1)) ^ (row & 7);
                LDSM_X4(bf[bt], b_base + 4u * (uint32_t)((row << 5) + (g << 2)));
            }
#pragma unroll
            for (int mt = 0; mt < 4; mt++)
#pragma unroll
                for (int nt = 0; nt < 4; nt++) {
                    uint32_t bb[2] = { bf[nt >> 1][(nt & 1) * 2],
                                       bf[nt >> 1][(nt & 1) * 2 + 1] };
                    MMA_TF32(acc[mt][nt], af[mt], bb);
                }
        }

        if (c + 1 < NCHUNK) {
            __syncthreads();   // everyone done reading buf^1 (chunk c-1)
            const uint32_t na = smb + (uint32_t)((buf ^ 1) * 8192) * 4u;
#pragma unroll
            for (int i = 0; i < 4; i++) {
                const uint32_t o = 4u * swz_idx(srow[i], sg[i] * 4);
                STS128(cvt_tf32(pa[i].x), cvt_tf32(pa[i].y), cvt_tf32(pa[i].z), cvt_tf32(pa[i].w),
                       na + o);
                STS128(cvt_tf32(pb[i].x), cvt_tf32(pb[i].y), cvt_tf32(pb[i].z), cvt_tf32(pb[i].w),
                       na + 4096u * 4u + o);
            }
            __syncthreads();
        }
    }

    // ---- epilogue ----
#pragma unroll
    for (int mt = 0; mt < 4; mt++) {
        const int r0 = bm + wm + mt * 16 + (lane >> 2);
#pragma unroll
        for (int nt = 0; nt < 4; nt++) {
            const int c0 = bn + wn + nt * 8 + ((lane & 3) << 1);
            const float2 bb = *(const float2*)(bias + c0);
            float2 o0 = { acc[mt][nt][0] + bb.x, acc[mt][nt][1] + bb.y };
            float2 o1 = { acc[mt][nt][2] + bb.x, acc[mt][nt][3] + bb.y };
            *(float2*)(C + (size_t)r0 * 1024 + c0)       = o0;
            *(float2*)(C + (size_t)(r0 + 8) * 1024 + c0) = o1;
        }
    }
}

// ---------------- fast exp on FMA pipe ----------------
__device__ __forceinline__ float fexp(float x) {
    float t = fmaxf(x * 1.4426950408889634f, -125.0f);
    float fi = floorf(t);
    float f  = t - fi;
    float r  = 0.0013333558f;
    r = r * f + 0.0096181291f;
    r = r * f + 0.0555041086f;
    r = r * f + 0.2402265069f;
    r = r * f + 0.6931471806f;
    r = r * f + 1.0f;
    int e = (int)fi;
    return __int_as_float((e + 127) << 23) * r;
}

// ---------------- Flash attention (fp32, online softmax, poly exp) ----------------
__global__ void __launch_bounds__(128) attn_kernel(
    const float* __restrict__ Q, const float* __restrict__ K,
    const float* __restrict__ V, float* __restrict__ O)
{
    __shared__ __align__(16) float Ks[64][64];
    __shared__ __align__(16) float Vs[64][64];

    const int tid = threadIdx.x;
    const int h   = blockIdx.y;
    const int b   = blockIdx.z;
    const int row = blockIdx.x * 128 + tid;
    const size_t base = (size_t)b * SEQ * D + (size_t)h * HD;

    float q[64], o[64];
#pragma unroll
    for (int d4 = 0; d4 < 16; d4++) {
        float4 t = *(const float4*)(Q + base + (size_t)row * D + d4 * 4);
        q[4 * d4 + 0] = t.x * 0.125f;
        q[4 * d4 + 1] = t.y * 0.125f;
        q[4 * d4 + 2] = t.z * 0.125f;
        q[4 * d4 + 3] = t.w * 0.125f;
    }
#pragma unroll
    for (int d = 0; d < 64; d++) o[d] = 0.0f;

    float m = -1e30f, l = 0.0f;

    for (int kt = 0; kt < SEQ / 64; kt++) {
        __syncthreads();
#pragma unroll
        for (int i = 0; i < 8; i++) {
            const int f = tid + i * 128;
            const int r = f >> 4;
            const int c = (f & 15) * 4;
            *(float4*)&Ks[r][c] = *(const float4*)(K + base + (size_t)(kt * 64 + r) * D + c);
            *(float4*)&Vs[r][c] = *(const float4*)(V + base + (size_t)(kt * 64 + r) * D + c);
        }
        __syncthreads();

#pragma unroll
        for (int c0 = 0; c0 < 64; c0 += 16) {
            float s[16];
            float cm = m;
#pragma unroll
            for (int jj = 0; jj < 16; jj++) {
                const float4* kr = (const float4*)&Ks[c0 + jj][0];
                float acc = 0.0f;
#pragma unroll
                for (int d4 = 0; d4 < 16; d4++) {
                    float4 kv = kr[d4];
                    acc += q[4 * d4 + 0] * kv.x;
                    acc += q[4 * d4 + 1] * kv.y;
                    acc += q[4 * d4 + 2] * kv.z;
                    acc += q[4 * d4 + 3] * kv.w;
                }
                s[jj] = acc;
                cm = fmaxf(cm, acc);
            }
            const float corr = fexp(m - cm);
            m = cm;
            l *= corr;
#pragma unroll
            for (int d = 0; d < 64; d++) o[d] *= corr;
#pragma unroll
            for (int jj = 0; jj < 16; jj++) {
                const float p = fexp(s[jj] - m);
                l += p;
                const float4* vr = (const float4*)&Vs[c0 + jj][0];
#pragma unroll
                for (int d4 = 0; d4 < 16; d4++) {
                    float4 vv = vr[d4];
                    o[4 * d4 + 0] += p * vv.x;
                    o[4 * d4 + 1] += p * vv.y;
                    o[4 * d4 + 2] += p * vv.z;
                    o[4 * d4 + 3] += p * vv.w;
                }
            }
        }
    }

    const float inv = 1.0f / l;
#pragma unroll
    for (int d4 = 0; d4 < 16; d4++) {
        float4 t;
        t.x = o[4 * d4 + 0] * inv;
        t.y = o[4 * d4 + 1] * inv;
        t.z = o[4 * d4 + 2] * inv;
        t.w = o[4 * d4 + 3] * inv;
        *(float4*)(O + base + (size_t)row * D + d4 * 4) = t;
    }
}

// ---------------- residual + LayerNorm ----------------
__global__ void __launch_bounds__(256) ln_kernel(
    const float* __restrict__ x, const float* __restrict__ y,
    const float* __restrict__ gamma, const float* __restrict__ beta,
    float* __restrict__ out)
{
    __shared__ float red[8];
    const int row = blockIdx.x;
    const int tid = threadIdx.x;

    float4 xv = ((const float4*)(x + (size_t)row * D))[tid];
    float4 yv = ((const float4*)(y + (size_t)row * D))[tid];
    float v[4] = {xv.x + yv.x, xv.y + yv.y, xv.z + yv.z, xv.w + yv.w};

    float s = v[0] + v[1] + v[2] + v[3];
#pragma unroll
    for (int off = 16; off; off >>= 1) s += __shfl_xor_sync(0xffffffffu, s, off);
    if ((tid & 31) == 0) red[tid >> 5] = s;
    __syncthreads();
    if (tid == 0) {
        float t = 0.0f;
        for (int i = 0; i < 8; i++) t += red[i];
        red[0] = t;
    }
    __syncthreads();
    const float mean = red[0] * (1.0f / 1024.0f);
    __syncthreads();

    float ss = 0.0f;
#pragma unroll
    for (int i = 0; i < 4; i++) {
        float d = v[i] - mean;
        ss += d * d;
    }
#pragma unroll
    for (int off = 16; off; off >>= 1) ss += __shfl_xor_sync(0xffffffffu, ss, off);
    if ((tid & 31) == 0) red[tid >> 5] = ss;
    __syncthreads();
    if (tid == 0) {
        float t = 0.0f;
        for (int i = 0; i < 8; i++) t += red[i];
        red[0] = t;
    }
    __syncthreads();
    const float rstd = rsqrtf(red[0] * (1.0f / 1024.0f) + 1e-6f);

    float4 gv = ((const float4*)gamma)[tid];
    float4 bv = ((const float4*)beta)[tid];
    float4 ov;
    ov.x = (v[0] - mean) * rstd * gv.x + bv.x;
    ov.y = (v[1] - mean) * rstd * gv.y + bv.y;
    ov.z = (v[2] - mean) * rstd * gv.z + bv.z;
    ov.w = (v[3] - mean) * rstd * gv.w + bv.w;
    ((float4*)(out + (size_t)row * D))[tid] = ov;
}

// ---------------- launch ----------------
extern "C" void kernel_launch(void* const* d_in, const int* in_sizes, int n_in,
                              void* d_out, int out_size)
{
    const float* x     = (const float*)d_in[0];
    const float* Wq    = (const float*)d_in[1];
    const float* bq    = (const float*)d_in[2];
    const float* Wk    = (const float*)d_in[3];
    const float* bk    = (const float*)d_in[4];
    const float* Wv    = (const float*)d_in[5];
    const float* bv    = (const float*)d_in[6];
    const float* Wo    = (const float*)d_in[7];
    const float* bo    = (const float*)d_in[8];
    const float* gamma = (const float*)d_in[9];
    const float* beta  = (const float*)d_in[10];
    float* out = (float*)d_out;

    float *qp, *kp, *vp, *cp, *ap;
    cudaGetSymbolAddress((void**)&qp, g_q);
    cudaGetSymbolAddress((void**)&kp, g_k);
    cudaGetSymbolAddress((void**)&vp, g_v);
    cudaGetSymbolAddress((void**)&cp, g_ctx);
    cudaGetSymbolAddress((void**)&ap, g_att);

    cudaFuncSetAttribute(gemm_mma, cudaFuncAttributeMaxDynamicSharedMemorySize, GEMM_SMEM);

    dim3 gg(8, 32);                 // N/128, M/128
    gemm_mma<<<gg, 256, GEMM_SMEM>>>(x, Wq, bq, qp);
    gemm_mma<<<gg, 256, GEMM_SMEM>>>(x, Wk, bk, kp);
    gemm_mma<<<gg, 256, GEMM_SMEM>>>(x, Wv, bv, vp);
    attn_kernel<<<dim3(16, 16, 2), 128>>>(qp, kp, vp, cp);
    gemm_mma<<<gg, 256, GEMM_SMEM>>>(cp, Wo, bo, ap);
    ln_kernel<<<4096, 256>>>(x, ap, gamma, beta, out);
}

// round 4
// speedup vs baseline: 5.1019x; 4.1169x over previous
#include <cuda_runtime.h>
#include <cstdint>

#define D   1024
#define SEQ 2048
#define BAT 2
#define H   16
#define HD  64
#define TOK (BAT * SEQ)   // 4096

// ---------------- scratch (no allocations allowed) ----------------
__device__ float g_q[TOK * D];
__device__ float g_k[TOK * D];
__device__ float g_v[TOK * D];
__device__ float g_ctx[TOK * D];
__device__ float g_att[TOK * D];

// ==================== helpers ====================
__device__ __forceinline__ uint32_t smem_u32(const void* p) {
    uint32_t a;
    asm("{ .reg .u64 t; cvta.to.shared.u64 t, %1; cvt.u32.u64 %0, t; }" : "=r"(a) : "l"(p));
    return a;
}

__device__ __forceinline__ uint32_t cvt_tf32(float x) {
    uint32_t u;
    asm("cvt.rna.tf32.f32 %0, %1;" : "=r"(u) : "f"(x));
    return u;
}

#define LDSM_X4(r, addr) \
    asm volatile("ldmatrix.sync.aligned.m8n8.x4.shared.b16 {%0,%1,%2,%3}, [%4];" \
                 : "=r"((r)[0]), "=r"((r)[1]), "=r"((r)[2]), "=r"((r)[3]) : "r"(addr))

#define STS128(a0, a1, a2, a3, addr) \
    asm volatile("st.shared.v4.b32 [%0], {%1, %2, %3, %4};" \
                 :: "r"(addr), "r"(a0), "r"(a1), "r"(a2), "r"(a3) : "memory")

#define LDS32(r, addr) \
    asm volatile("ld.shared.b32 %0, [%1];" : "=r"(r) : "r"(addr))

#define MMA_TF32(acc, a, b) \
    asm volatile("mma.sync.aligned.m16n8k8.row.col.f32.tf32.tf32.f32 " \
                 "{%0,%1,%2,%3}, {%4,%5,%6,%7}, {%8,%9}, {%0,%1,%2,%3};" \
                 : "+f"((acc)[0]), "+f"((acc)[1]), "+f"((acc)[2]), "+f"((acc)[3]) \
                 : "r"((a)[0]), "r"((a)[1]), "r"((a)[2]), "r"((a)[3]), \
                   "r"((b)[0]), "r"((b)[1]))

#define CP_ASYNC16(smem, gmem) \
    asm volatile("cp.async.ca.shared.global [%0], [%1], 16;" :: "r"(smem), "l"(gmem) : "memory")
#define CP_COMMIT asm volatile("cp.async.commit_group;" ::: "memory")
#define CP_WAIT1  asm volatile("cp.async.wait_group 1;" ::: "memory")
#define CP_WAIT0  asm volatile("cp.async.wait_group 0;" ::: "memory")

// ---------------- fast exp on FMA pipe ----------------
__device__ __forceinline__ float fexp(float x) {
    float t = fmaxf(x * 1.4426950408889634f, -125.0f);
    float fi = floorf(t);
    float f  = t - fi;
    float r  = 0.0013333558f;
    r = r * f + 0.0096181291f;
    r = r * f + 0.0555041086f;
    r = r * f + 0.2402265069f;
    r = r * f + 0.6931471806f;
    r = r * f + 1.0f;
    int e = (int)fi;
    return __int_as_float((e + 127) << 23) * r;
}

// ==================== mma.sync tf32 GEMM (unchanged, proven) ====================
#define BK 32
#define NCHUNK (1024 / BK)
#define GEMM_SMEM (16384 * 4)   // 65536 B

__device__ __forceinline__ uint32_t swz_idx(int row, int k) {
    int g = (k >> 2) ^ (row & 7);
    return (uint32_t)((row << 5) + (g << 2) + (k & 3));
}

__global__ void __launch_bounds__(256) gemm_mma(
    const float* __restrict__ A, const float* __restrict__ W,
    const float* __restrict__ bias, float* __restrict__ C)
{
    extern __shared__ float sm[];
    const uint32_t smb = smem_u32(sm);

    const int tid  = threadIdx.x;
    const int lane = tid & 31;
    const int wid  = tid >> 5;
    const int wm   = (wid >> 2) * 64;
    const int wn   = (wid & 3) * 32;
    const int bm   = blockIdx.y * 128;
    const int bn   = blockIdx.x * 128;

    float acc[4][4][4];
#pragma unroll
    for (int mt = 0; mt < 4; mt++)
#pragma unroll
        for (int nt = 0; nt < 4; nt++)
#pragma unroll
            for (int r = 0; r < 4; r++) acc[mt][nt][r] = 0.0f;

    int srow[4], sg[4];
#pragma unroll
    for (int i = 0; i < 4; i++) {
        const int lin = tid + i * 256;
        srow[i] = lin >> 3;
        sg[i]   = lin & 7;
    }

#pragma unroll
    for (int i = 0; i < 4; i++) {
        const int r = srow[i], g = sg[i];
        float4 av = *(const float4*)(A + (size_t)(bm + r) * 1024 + g * 4);
        STS128(cvt_tf32(av.x), cvt_tf32(av.y), cvt_tf32(av.z), cvt_tf32(av.w),
               smb + 4u * swz_idx(r, g * 4));
        float4 wv = *(const float4*)(W + (size_t)(bn + r) * 1024 + g * 4);
        STS128(cvt_tf32(wv.x), cvt_tf32(wv.y), cvt_tf32(wv.z), cvt_tf32(wv.w),
               smb + 4u * (4096u + swz_idx(r, g * 4)));
    }
    __syncthreads();

    for (int c = 0; c < NCHUNK; c++) {
        const int buf = c & 1;
        const uint32_t a_base = smb + (uint32_t)(buf * 8192) * 4u;
        const uint32_t b_base = a_base + 4096u * 4u;

        float4 pa[4], pb[4];
        if (c + 1 < NCHUNK) {
            const int k0 = (c + 1) * BK;
#pragma unroll
            for (int i = 0; i < 4; i++) {
                pa[i] = *(const float4*)(A + (size_t)(bm + srow[i]) * 1024 + k0 + sg[i] * 4);
                pb[i] = *(const float4*)(W + (size_t)(bn + srow[i]) * 1024 + k0 + sg[i] * 4);
            }
        }

#pragma unroll
        for (int kk8 = 0; kk8 < 4; kk8++) {
            uint32_t af[4][4];
#pragma unroll
            for (int mt = 0; mt < 4; mt++) {
                const int row = wm + mt * 16 + (lane & 15);
                const int g = (kk8 * 2 + (lane >> 4)) ^ (row & 7);
                LDSM_X4(af[mt], a_base + 4u * (uint32_t)((row << 5) + (g << 2)));
            }
            uint32_t bf[2][4];
#pragma unroll
            for (int bt = 0; bt < 2; bt++) {
                const int row = wn + bt * 16 + ((lane >> 4) << 3) + (lane & 7);
                const int g = (kk8 * 2 + ((lane >> 3) & 1)) ^ (row & 7);
                LDSM_X4(bf[bt], b_base + 4u * (uint32_t)((row << 5) + (g << 2)));
            }
#pragma unroll
            for (int mt = 0; mt < 4; mt++)
#pragma unroll
                for (int nt = 0; nt < 4; nt++) {
                    uint32_t bb[2] = { bf[nt >> 1][(nt & 1) * 2],
                                       bf[nt >> 1][(nt & 1) * 2 + 1] };
                    MMA_TF32(acc[mt][nt], af[mt], bb);
                }
        }

        if (c + 1 < NCHUNK) {
            __syncthreads();
            const uint32_t na = smb + (uint32_t)((buf ^ 1) * 8192) * 4u;
#pragma unroll
            for (int i = 0; i < 4; i++) {
                const uint32_t o = 4u * swz_idx(srow[i], sg[i] * 4);
                STS128(cvt_tf32(pa[i].x), cvt_tf32(pa[i].y), cvt_tf32(pa[i].z), cvt_tf32(pa[i].w),
                       na + o);
                STS128(cvt_tf32(pb[i].x), cvt_tf32(pb[i].y), cvt_tf32(pb[i].z), cvt_tf32(pb[i].w),
                       na + 4096u * 4u + o);
            }
            __syncthreads();
        }
    }

#pragma unroll
    for (int mt = 0; mt < 4; mt++) {
        const int r0 = bm + wm + mt * 16 + (lane >> 2);
#pragma unroll
        for (int nt = 0; nt < 4; nt++) {
            const int c0 = bn + wn + nt * 8 + ((lane & 3) << 1);
            const float2 bb = *(const float2*)(bias + c0);
            float2 o0 = { acc[mt][nt][0] + bb.x, acc[mt][nt][1] + bb.y };
            float2 o1 = { acc[mt][nt][2] + bb.x, acc[mt][nt][3] + bb.y };
            *(float2*)(C + (size_t)r0 * 1024 + c0)       = o0;
            *(float2*)(C + (size_t)(r0 + 8) * 1024 + c0) = o1;
        }
    }
}

// ==================== mma.sync tf32 flash attention ====================
// CTA: 64 q rows, 4 warps (16 rows each). K/V tiles 64 keys, double buffered.
// smem floats: Q 4096 | K0 4096 | K1 4096 | V0 4096 | V1 4096 = 81920 B
#define ATTN_SMEM (20480 * 4)

__global__ void __launch_bounds__(128) attn_mma(
    const float* __restrict__ Q, const float* __restrict__ K,
    const float* __restrict__ V, float* __restrict__ O)
{
    extern __shared__ float smf[];
    const uint32_t smb = smem_u32(smf);

    const int tid  = threadIdx.x;
    const int lane = tid & 31;
    const int w    = tid >> 5;
    const int q0   = blockIdx.x * 64;
    const int h    = blockIdx.y;
    const int b    = blockIdx.z;
    const size_t base = (size_t)b * SEQ * D + (size_t)h * HD;

    // ---- stage Q (scale folded, tf32 cvt), swizzled 64-float rows ----
#pragma unroll
    for (int j = 0; j < 8; j++) {
        const int idx = tid + j * 128;
        const int r = idx >> 4, g = idx & 15;
        float4 t = *(const float4*)(Q + base + (size_t)(q0 + r) * D + g * 4);
        const uint32_t off = (uint32_t)(r * 64 + ((g ^ (r & 7)) << 2));
        STS128(cvt_tf32(t.x * 0.125f), cvt_tf32(t.y * 0.125f),
               cvt_tf32(t.z * 0.125f), cvt_tf32(t.w * 0.125f), smb + off * 4u);
    }

    // ---- stage K/V tile 0 into buffer 0 (cp.async) ----
    {
#pragma unroll
        for (int j = 0; j < 8; j++) {
            const int idx = tid + j * 128;
            const int s = idx >> 4, g = idx & 15;
            const uint32_t koff = (uint32_t)(s * 64 + ((g ^ (s & 7)) << 2));
            CP_ASYNC16(smb + (4096u + koff) * 4u, K + base + (size_t)s * D + g * 4);
            const uint32_t voff = (uint32_t)(g * 256 + ((s ^ ((g & 1) << 2)) << 2));
            CP_ASYNC16(smb + (12288u + voff) * 4u, V + base + (size_t)s * D + g * 4);
        }
    }
    CP_COMMIT;
    __syncthreads();

    // ---- load Q fragments once ----
    uint32_t qf[8][4];
#pragma unroll
    for (int kk = 0; kk < 8; kk++) {
        const int row = w * 16 + (lane & 15);
        const int g = (kk * 2 + (lane >> 4)) ^ (row & 7);
        LDSM_X4(qf[kk], smb + 4u * (uint32_t)(row * 64 + g * 4));
    }

    float m0 = -1e30f, m1 = -1e30f, l0 = 0.0f, l1 = 0.0f;
    float oacc[8][4];
#pragma unroll
    for (int nd = 0; nd < 8; nd++)
#pragma unroll
        for (int r = 0; r < 4; r++) oacc[nd][r] = 0.0f;

    for (int it = 0; it < SEQ / 64; it++) {
        const int buf = it & 1;
        if (it + 1 < SEQ / 64) {
            const int kt = it + 1;
            const uint32_t kb = smb + (4096u + (uint32_t)(buf ^ 1) * 4096u) * 4u;
            const uint32_t vb = smb + (12288u + (uint32_t)(buf ^ 1) * 4096u) * 4u;
#pragma unroll
            for (int j = 0; j < 8; j++) {
                const int idx = tid + j * 128;
                const int s = idx >> 4, g = idx & 15;
                const uint32_t koff = (uint32_t)(s * 64 + ((g ^ (s & 7)) << 2));
                CP_ASYNC16(kb + koff * 4u, K + base + (size_t)(kt * 64 + s) * D + g * 4);
                const uint32_t voff = (uint32_t)(g * 256 + ((s ^ ((g & 1) << 2)) << 2));
                CP_ASYNC16(vb + voff * 4u, V + base + (size_t)(kt * 64 + s) * D + g * 4);
            }
            CP_COMMIT;
            CP_WAIT1;
        } else {
            CP_WAIT0;
        }
        __syncthreads();

        const uint32_t kb = smb + (4096u + (uint32_t)buf * 4096u) * 4u;
        const uint32_t vb = smb + (12288u + (uint32_t)buf * 4096u) * 4u;

        // ---- S = Q @ K^T (16 x 64 per warp) ----
        float sacc[8][4];
#pragma unroll
        for (int nt = 0; nt < 8; nt++)
#pragma unroll
            for (int r = 0; r < 4; r++) sacc[nt][r] = 0.0f;

#pragma unroll
        for (int kk = 0; kk < 8; kk++) {
            uint32_t bf[4][4];
#pragma unroll
            for (int bt = 0; bt < 4; bt++) {
                const int row = bt * 16 + ((lane >> 4) << 3) + (lane & 7);
                const int g = (kk * 2 + ((lane >> 3) & 1)) ^ (row & 7);
                LDSM_X4(bf[bt], kb + 4u * (uint32_t)(row * 64 + g * 4));
            }
#pragma unroll
            for (int nt = 0; nt < 8; nt++) {
                uint32_t bb[2] = { bf[nt >> 1][(nt & 1) * 2],
                                   bf[nt >> 1][(nt & 1) * 2 + 1] };
                MMA_TF32(sacc[nt], qf[kk], bb);
            }
        }

        // ---- online softmax (rows lane>>2 and lane>>2 + 8) ----
        float mx0 = sacc[0][0], mx1 = sacc[0][2];
#pragma unroll
        for (int nt = 0; nt < 8; nt++) {
            mx0 = fmaxf(mx0, fmaxf(sacc[nt][0], sacc[nt][1]));
            mx1 = fmaxf(mx1, fmaxf(sacc[nt][2], sacc[nt][3]));
        }
        mx0 = fmaxf(mx0, __shfl_xor_sync(0xffffffffu, mx0, 1));
        mx0 = fmaxf(mx0, __shfl_xor_sync(0xffffffffu, mx0, 2));
        mx1 = fmaxf(mx1, __shfl_xor_sync(0xffffffffu, mx1, 1));
        mx1 = fmaxf(mx1, __shfl_xor_sync(0xffffffffu, mx1, 2));

        const float nm0 = fmaxf(m0, mx0);
        const float nm1 = fmaxf(m1, mx1);
        const float c0 = fexp(m0 - nm0);
        const float c1 = fexp(m1 - nm1);
        m0 = nm0; m1 = nm1;
        l0 *= c0;  l1 *= c1;
#pragma unroll
        for (int nd = 0; nd < 8; nd++) {
            oacc[nd][0] *= c0; oacc[nd][1] *= c0;
            oacc[nd][2] *= c1; oacc[nd][3] *= c1;
        }
#pragma unroll
        for (int nt = 0; nt < 8; nt++) {
            const float p0 = fexp(sacc[nt][0] - m0);
            const float p1 = fexp(sacc[nt][1] - m0);
            const float p2 = fexp(sacc[nt][2] - m1);
            const float p3 = fexp(sacc[nt][3] - m1);
            l0 += p0 + p1;
            l1 += p2 + p3;
            sacc[nt][0] = p0; sacc[nt][1] = p1;
            sacc[nt][2] = p2; sacc[nt][3] = p3;
        }

        // ---- O += P @ V ----
#pragma unroll
        for (int kc = 0; kc < 8; kc++) {
            const uint32_t p0 = cvt_tf32(sacc[kc][0]);
            const uint32_t p1 = cvt_tf32(sacc[kc][1]);
            const uint32_t p2 = cvt_tf32(sacc[kc][2]);
            const uint32_t p3 = cvt_tf32(sacc[kc][3]);
            const int src0 = (lane & 3) >> 1;
            uint32_t a[4], lo, hi;
            lo = __shfl_sync(0xffffffffu, p0, src0, 4);
            hi = __shfl_sync(0xffffffffu, p1, src0, 4);
            a[0] = (lane & 1) ? hi : lo;
            lo = __shfl_sync(0xffffffffu, p2, src0, 4);
            hi = __shfl_sync(0xffffffffu, p3, src0, 4);
            a[1] = (lane & 1) ? hi : lo;
            lo = __shfl_sync(0xffffffffu, p0, src0 + 2, 4);
            hi = __shfl_sync(0xffffffffu, p1, src0 + 2, 4);
            a[2] = (lane & 1) ? hi : lo;
            lo = __shfl_sync(0xffffffffu, p2, src0 + 2, 4);
            hi = __shfl_sync(0xffffffffu, p3, src0 + 2, 4);
            a[3] = (lane & 1) ? hi : lo;

            const int dl = lane >> 2;            // 0..7
            const int s_ = kc * 8 + (lane & 3);
#pragma unroll
            for (int nd = 0; nd < 8; nd++) {
                const int gd = nd * 2 + (dl >> 2);
                const int x  = (gd & 1) << 2;
                const uint32_t off0 = (uint32_t)(gd * 256 + ((s_ ^ x) << 2) + (dl & 3));
                const uint32_t off1 = (uint32_t)(gd * 256 + (((s_ + 4) ^ x) << 2) + (dl & 3));
                uint32_t bb[2];
                LDS32(bb[0], vb + off0 * 4u);
                LDS32(bb[1], vb + off1 * 4u);
                MMA_TF32(oacc[nd], a, bb);
            }
        }
        __syncthreads();
    }

    // ---- epilogue ----
    l0 += __shfl_xor_sync(0xffffffffu, l0, 1);
    l0 += __shfl_xor_sync(0xffffffffu, l0, 2);
    l1 += __shfl_xor_sync(0xffffffffu, l1, 1);
    l1 += __shfl_xor_sync(0xffffffffu, l1, 2);
    const float i0 = 1.0f / l0;
    const float i1 = 1.0f / l1;
    const int r0 = q0 + w * 16 + (lane >> 2);
#pragma unroll
    for (int nd = 0; nd < 8; nd++) {
        const int c = nd * 8 + (lane & 3) * 2;
        float2 v0 = { oacc[nd][0] * i0, oacc[nd][1] * i0 };
        float2 v1 = { oacc[nd][2] * i1, oacc[nd][3] * i1 };
        *(float2*)(O + base + (size_t)r0 * D + c)       = v0;
        *(float2*)(O + base + (size_t)(r0 + 8) * D + c) = v1;
    }
}

// ---------------- residual + LayerNorm ----------------
__global__ void __launch_bounds__(256) ln_kernel(
    const float* __restrict__ x, const float* __restrict__ y,
    const float* __restrict__ gamma, const float* __restrict__ beta,
    float* __restrict__ out)
{
    __shared__ float red[8];
    const int row = blockIdx.x;
    const int tid = threadIdx.x;

    float4 xv = ((const float4*)(x + (size_t)row * D))[tid];
    float4 yv = ((const float4*)(y + (size_t)row * D))[tid];
    float v[4] = {xv.x + yv.x, xv.y + yv.y, xv.z + yv.z, xv.w + yv.w};

    float s = v[0] + v[1] + v[2] + v[3];
#pragma unroll
    for (int off = 16; off; off >>= 1) s += __shfl_xor_sync(0xffffffffu, s, off);
    if ((tid & 31) == 0) red[tid >> 5] = s;
    __syncthreads();
    if (tid == 0) {
        float t = 0.0f;
        for (int i = 0; i < 8; i++) t += red[i];
        red[0] = t;
    }
    __syncthreads();
    const float mean = red[0] * (1.0f / 1024.0f);
    __syncthreads();

    float ss = 0.0f;
#pragma unroll
    for (int i = 0; i < 4; i++) {
        float d = v[i] - mean;
        ss += d * d;
    }
#pragma unroll
    for (int off = 16; off; off >>= 1) ss += __shfl_xor_sync(0xffffffffu, ss, off);
    if ((tid & 31) == 0) red[tid >> 5] = ss;
    __syncthreads();
    if (tid == 0) {
        float t = 0.0f;
        for (int i = 0; i < 8; i++) t += red[i];
        red[0] = t;
    }
    __syncthreads();
    const float rstd = rsqrtf(red[0] * (1.0f / 1024.0f) + 1e-6f);

    float4 gv = ((const float4*)gamma)[tid];
    float4 bv = ((const float4*)beta)[tid];
    float4 ov;
    ov.x = (v[0] - mean) * rstd * gv.x + bv.x;
    ov.y = (v[1] - mean) * rstd * gv.y + bv.y;
    ov.z = (v[2] - mean) * rstd * gv.z + bv.z;
    ov.w = (v[3] - mean) * rstd * gv.w + bv.w;
    ((float4*)(out + (size_t)row * D))[tid] = ov;
}

// ---------------- launch ----------------
extern "C" void kernel_launch(void* const* d_in, const int* in_sizes, int n_in,
                              void* d_out, int out_size)
{
    const float* x     = (const float*)d_in[0];
    const float* Wq    = (const float*)d_in[1];
    const float* bq    = (const float*)d_in[2];
    const float* Wk    = (const float*)d_in[3];
    const float* bk    = (const float*)d_in[4];
    const float* Wv    = (const float*)d_in[5];
    const float* bv    = (const float*)d_in[6];
    const float* Wo    = (const float*)d_in[7];
    const float* bo    = (const float*)d_in[8];
    const float* gamma = (const float*)d_in[9];
    const float* beta  = (const float*)d_in[10];
    float* out = (float*)d_out;

    float *qp, *kp, *vp, *cp, *ap;
    cudaGetSymbolAddress((void**)&qp, g_q);
    cudaGetSymbolAddress((void**)&kp, g_k);
    cudaGetSymbolAddress((void**)&vp, g_v);
    cudaGetSymbolAddress((void**)&cp, g_ctx);
    cudaGetSymbolAddress((void**)&ap, g_att);

    cudaFuncSetAttribute(gemm_mma, cudaFuncAttributeMaxDynamicSharedMemorySize, GEMM_SMEM);
    cudaFuncSetAttribute(attn_mma, cudaFuncAttributeMaxDynamicSharedMemorySize, ATTN_SMEM);

    dim3 gg(8, 32);
    gemm_mma<<<gg, 256, GEMM_SMEM>>>(x, Wq, bq, qp);
    gemm_mma<<<gg, 256, GEMM_SMEM>>>(x, Wk, bk, kp);
    gemm_mma<<<gg, 256, GEMM_SMEM>>>(x, Wv, bv, vp);
    attn_mma<<<dim3(32, 16, 2), 128, ATTN_SMEM>>>(qp, kp, vp, cp);
    gemm_mma<<<gg, 256, GEMM_SMEM>>>(cp, Wo, bo, ap);
    ln_kernel<<<4096, 256>>>(x, ap, gamma, beta, out);
}

// round 5
// speedup vs baseline: 5.3372x; 1.0461x over previous
#include <cuda_runtime.h>
#include <cstdint>

#define D   1024
#define SEQ 2048
#define BAT 2
#define H   16
#define HD  64
#define TOK (BAT * SEQ)   // 4096

// ---------------- scratch (no allocations allowed) ----------------
__device__ float g_q[TOK * D];
__device__ float g_k[TOK * D];
__device__ float g_v[TOK * D];
__device__ float g_vt[TOK * D];   // V transposed: [b][h][d][s]
__device__ float g_ctx[TOK * D];
__device__ float g_att[TOK * D];

// ==================== helpers ====================
__device__ __forceinline__ uint32_t smem_u32(const void* p) {
    uint32_t a;
    asm("{ .reg .u64 t; cvta.to.shared.u64 t, %1; cvt.u32.u64 %0, t; }" : "=r"(a) : "l"(p));
    return a;
}

__device__ __forceinline__ uint32_t cvt_tf32(float x) {
    uint32_t u;
    asm("cvt.rna.tf32.f32 %0, %1;" : "=r"(u) : "f"(x));
    return u;
}

#define LDSM_X4(r, addr) \
    asm volatile("ldmatrix.sync.aligned.m8n8.x4.shared.b16 {%0,%1,%2,%3}, [%4];" \
                 : "=r"((r)[0]), "=r"((r)[1]), "=r"((r)[2]), "=r"((r)[3]) : "r"(addr))

#define STS128(a0, a1, a2, a3, addr) \
    asm volatile("st.shared.v4.b32 [%0], {%1, %2, %3, %4};" \
                 :: "r"(addr), "r"(a0), "r"(a1), "r"(a2), "r"(a3) : "memory")

#define MMA_TF32(acc, a, b) \
    asm volatile("mma.sync.aligned.m16n8k8.row.col.f32.tf32.tf32.f32 " \
                 "{%0,%1,%2,%3}, {%4,%5,%6,%7}, {%8,%9}, {%0,%1,%2,%3};" \
                 : "+f"((acc)[0]), "+f"((acc)[1]), "+f"((acc)[2]), "+f"((acc)[3]) \
                 : "r"((a)[0]), "r"((a)[1]), "r"((a)[2]), "r"((a)[3]), \
                   "r"((b)[0]), "r"((b)[1]))

#define CP_ASYNC16(smem, gmem) \
    asm volatile("cp.async.ca.shared.global [%0], [%1], 16;" :: "r"(smem), "l"(gmem) : "memory")
#define CP_COMMIT asm volatile("cp.async.commit_group;" ::: "memory")
#define CP_WAIT1  asm volatile("cp.async.wait_group 1;" ::: "memory")
#define CP_WAIT0  asm volatile("cp.async.wait_group 0;" ::: "memory")

// ---------------- fast exp on FMA pipe ----------------
__device__ __forceinline__ float fexp(float x) {
    float t = fmaxf(x * 1.4426950408889634f, -125.0f);
    float fi = floorf(t);
    float f  = t - fi;
    float r  = 0.0013333558f;
    r = r * f + 0.0096181291f;
    r = r * f + 0.0555041086f;
    r = r * f + 0.2402265069f;
    r = r * f + 0.6931471806f;
    r = r * f + 1.0f;
    int e = (int)fi;
    return __int_as_float((e + 127) << 23) * r;
}

// ==================== mma.sync tf32 GEMM (unchanged, proven) ====================
#define BK 32
#define NCHUNK (1024 / BK)
#define GEMM_SMEM (16384 * 4)   // 65536 B

__device__ __forceinline__ uint32_t swz_idx(int row, int k) {
    int g = (k >> 2) ^ (row & 7);
    return (uint32_t)((row << 5) + (g << 2) + (k & 3));
}

__global__ void __launch_bounds__(256) gemm_mma(
    const float* __restrict__ A, const float* __restrict__ W,
    const float* __restrict__ bias, float* __restrict__ C)
{
    extern __shared__ float sm[];
    const uint32_t smb = smem_u32(sm);

    const int tid  = threadIdx.x;
    const int lane = tid & 31;
    const int wid  = tid >> 5;
    const int wm   = (wid >> 2) * 64;
    const int wn   = (wid & 3) * 32;
    const int bm   = blockIdx.y * 128;
    const int bn   = blockIdx.x * 128;

    float acc[4][4][4];
#pragma unroll
    for (int mt = 0; mt < 4; mt++)
#pragma unroll
        for (int nt = 0; nt < 4; nt++)
#pragma unroll
            for (int r = 0; r < 4; r++) acc[mt][nt][r] = 0.0f;

    int srow[4], sg[4];
#pragma unroll
    for (int i = 0; i < 4; i++) {
        const int lin = tid + i * 256;
        srow[i] = lin >> 3;
        sg[i]   = lin & 7;
    }

#pragma unroll
    for (int i = 0; i < 4; i++) {
        const int r = srow[i], g = sg[i];
        float4 av = *(const float4*)(A + (size_t)(bm + r) * 1024 + g * 4);
        STS128(cvt_tf32(av.x), cvt_tf32(av.y), cvt_tf32(av.z), cvt_tf32(av.w),
               smb + 4u * swz_idx(r, g * 4));
        float4 wv = *(const float4*)(W + (size_t)(bn + r) * 1024 + g * 4);
        STS128(cvt_tf32(wv.x), cvt_tf32(wv.y), cvt_tf32(wv.z), cvt_tf32(wv.w),
               smb + 4u * (4096u + swz_idx(r, g * 4)));
    }
    __syncthreads();

    for (int c = 0; c < NCHUNK; c++) {
        const int buf = c & 1;
        const uint32_t a_base = smb + (uint32_t)(buf * 8192) * 4u;
        const uint32_t b_base = a_base + 4096u * 4u;

        float4 pa[4], pb[4];
        if (c + 1 < NCHUNK) {
            const int k0 = (c + 1) * BK;
#pragma unroll
            for (int i = 0; i < 4; i++) {
                pa[i] = *(const float4*)(A + (size_t)(bm + srow[i]) * 1024 + k0 + sg[i] * 4);
                pb[i] = *(const float4*)(W + (size_t)(bn + srow[i]) * 1024 + k0 + sg[i] * 4);
            }
        }

#pragma unroll
        for (int kk8 = 0; kk8 < 4; kk8++) {
            uint32_t af[4][4];
#pragma unroll
            for (int mt = 0; mt < 4; mt++) {
                const int row = wm + mt * 16 + (lane & 15);
                const int g = (kk8 * 2 + (lane >> 4)) ^ (row & 7);
                LDSM_X4(af[mt], a_base + 4u * (uint32_t)((row << 5) + (g << 2)));
            }
            uint32_t bf[2][4];
#pragma unroll
            for (int bt = 0; bt < 2; bt++) {
                const int row = wn + bt * 16 + ((lane >> 4) << 3) + (lane & 7);
                const int g = (kk8 * 2 + ((lane >> 3) & 1)) ^ (row & 7);
                LDSM_X4(bf[bt], b_base + 4u * (uint32_t)((row << 5) + (g << 2)));
            }
#pragma unroll
            for (int mt = 0; mt < 4; mt++)
#pragma unroll
                for (int nt = 0; nt < 4; nt++) {
                    uint32_t bb[2] = { bf[nt >> 1][(nt & 1) * 2],
                                       bf[nt >> 1][(nt & 1) * 2 + 1] };
                    MMA_TF32(acc[mt][nt], af[mt], bb);
                }
        }

        if (c + 1 < NCHUNK) {
            __syncthreads();
            const uint32_t na = smb + (uint32_t)((buf ^ 1) * 8192) * 4u;
#pragma unroll
            for (int i = 0; i < 4; i++) {
                const uint32_t o = 4u * swz_idx(srow[i], sg[i] * 4);
                STS128(cvt_tf32(pa[i].x), cvt_tf32(pa[i].y), cvt_tf32(pa[i].z), cvt_tf32(pa[i].w),
                       na + o);
                STS128(cvt_tf32(pb[i].x), cvt_tf32(pb[i].y), cvt_tf32(pb[i].z), cvt_tf32(pb[i].w),
                       na + 4096u * 4u + o);
            }
            __syncthreads();
        }
    }

#pragma unroll
    for (int mt = 0; mt < 4; mt++) {
        const int r0 = bm + wm + mt * 16 + (lane >> 2);
#pragma unroll
        for (int nt = 0; nt < 4; nt++) {
            const int c0 = bn + wn + nt * 8 + ((lane & 3) << 1);
            const float2 bb = *(const float2*)(bias + c0);
            float2 o0 = { acc[mt][nt][0] + bb.x, acc[mt][nt][1] + bb.y };
            float2 o1 = { acc[mt][nt][2] + bb.x, acc[mt][nt][3] + bb.y };
            *(float2*)(C + (size_t)r0 * 1024 + c0)       = o0;
            *(float2*)(C + (size_t)(r0 + 8) * 1024 + c0) = o1;
        }
    }
}

// ==================== V transpose: [b][s][h*64+d] -> [b][h][d][s] ====================
__global__ void __launch_bounds__(256) vtrans(
    const float* __restrict__ V, float* __restrict__ VT)
{
    __shared__ float t[64][65];
    const int st  = blockIdx.x;   // s tile (64 each)
    const int h   = blockIdx.y;
    const int b   = blockIdx.z;
    const int tid = threadIdx.x;

    const float* src = V + (size_t)b * SEQ * D + (size_t)(st * 64) * D + h * 64;
    const int d4 = (tid & 15) * 4;
    const int sr = tid >> 4;
#pragma unroll
    for (int p = 0; p < 4; p++) {
        const int s = sr + p * 16;
        float4 v = *(const float4*)(src + (size_t)s * D + d4);
        t[s][d4 + 0] = v.x; t[s][d4 + 1] = v.y;
        t[s][d4 + 2] = v.z; t[s][d4 + 3] = v.w;
    }
    __syncthreads();

    float* dst = VT + (size_t)(b * H + h) * 64 * SEQ + (size_t)st * 64;
    const int s4 = (tid & 15) * 4;
    const int dr = tid >> 4;
#pragma unroll
    for (int p = 0; p < 4; p++) {
        const int d = dr + p * 16;
        float4 o = { t[s4 + 0][d], t[s4 + 1][d], t[s4 + 2][d], t[s4 + 3][d] };
        *(float4*)(dst + (size_t)d * SEQ + s4) = o;
    }
}

// ==================== mma.sync tf32 flash attention ====================
// CTA: 128 q rows, 8 warps (16 rows each). K/V^T tiles 64 keys, double buffered.
// smem floats: Q 8192 | K0 4096 | K1 4096 | VT0 4096 | VT1 4096 = 98304 B
#define ATTN_SMEM (24576 * 4)

__global__ void __launch_bounds__(256) attn_mma(
    const float* __restrict__ Q, const float* __restrict__ K,
    const float* __restrict__ VT, float* __restrict__ O)
{
    extern __shared__ float smf[];
    const uint32_t smb = smem_u32(smf);

    const int tid  = threadIdx.x;
    const int lane = tid & 31;
    const int w    = tid >> 5;
    const int q0   = blockIdx.x * 128;
    const int h    = blockIdx.y;
    const int b    = blockIdx.z;
    const size_t base   = (size_t)b * SEQ * D + (size_t)h * HD;
    const size_t vtbase = (size_t)(b * H + h) * 64 * SEQ;

    // ---- stage Q (scale folded, tf32 cvt), swizzled 64-float rows ----
#pragma unroll
    for (int j = 0; j < 8; j++) {
        const int idx = tid + j * 256;
        const int r = idx >> 4, g = idx & 15;
        float4 t = *(const float4*)(Q + base + (size_t)(q0 + r) * D + g * 4);
        const uint32_t off = (uint32_t)(r * 64 + ((g ^ (r & 7)) << 2));
        STS128(cvt_tf32(t.x * 0.125f), cvt_tf32(t.y * 0.125f),
               cvt_tf32(t.z * 0.125f), cvt_tf32(t.w * 0.125f), smb + off * 4u);
    }

    // ---- stage K/V^T tile 0 into buffer 0 (cp.async) ----
#pragma unroll
    for (int j = 0; j < 4; j++) {
        const int idx = tid + j * 256;
        const int r = idx >> 4, g = idx & 15;
        const uint32_t off = (uint32_t)(r * 64 + ((g ^ (r & 7)) << 2));
        CP_ASYNC16(smb + (8192u + off) * 4u, K + base + (size_t)r * D + g * 4);
        CP_ASYNC16(smb + (16384u + off) * 4u, VT + vtbase + (size_t)r * SEQ + g * 4);
    }
    CP_COMMIT;
    __syncthreads();

    // ---- load Q fragments once ----
    uint32_t qf[8][4];
#pragma unroll
    for (int kk = 0; kk < 8; kk++) {
        const int row = w * 16 + (lane & 15);
        const int g = (kk * 2 + (lane >> 4)) ^ (row & 7);
        LDSM_X4(qf[kk], smb + 4u * (uint32_t)(row * 64 + g * 4));
    }

    float m0 = -1e30f, m1 = -1e30f, l0 = 0.0f, l1 = 0.0f;
    float oacc[8][4];
#pragma unroll
    for (int nd = 0; nd < 8; nd++)
#pragma unroll
        for (int r = 0; r < 4; r++) oacc[nd][r] = 0.0f;

    for (int it = 0; it < SEQ / 64; it++) {
        const int buf = it & 1;
        if (it + 1 < SEQ / 64) {
            const int kt = it + 1;
            const uint32_t kb = smb + (8192u + (uint32_t)(buf ^ 1) * 4096u) * 4u;
            const uint32_t vb = smb + (16384u + (uint32_t)(buf ^ 1) * 4096u) * 4u;
#pragma unroll
            for (int j = 0; j < 4; j++) {
                const int idx = tid + j * 256;
                const int r = idx >> 4, g = idx & 15;
                const uint32_t off = (uint32_t)(r * 64 + ((g ^ (r & 7)) << 2));
                CP_ASYNC16(kb + off * 4u, K + base + (size_t)(kt * 64 + r) * D + g * 4);
                CP_ASYNC16(vb + off * 4u, VT + vtbase + (size_t)r * SEQ + kt * 64 + g * 4);
            }
            CP_COMMIT;
            CP_WAIT1;
        } else {
            CP_WAIT0;
        }
        __syncthreads();

        const uint32_t kb = smb + (8192u + (uint32_t)buf * 4096u) * 4u;
        const uint32_t vb = smb + (16384u + (uint32_t)buf * 4096u) * 4u;

        // ---- S = Q @ K^T (16 x 64 per warp) ----
        float sacc[8][4];
#pragma unroll
        for (int nt = 0; nt < 8; nt++)
#pragma unroll
            for (int r = 0; r < 4; r++) sacc[nt][r] = 0.0f;

#pragma unroll
        for (int kk = 0; kk < 8; kk++) {
            uint32_t bf[4][4];
#pragma unroll
            for (int bt = 0; bt < 4; bt++) {
                const int row = bt * 16 + ((lane >> 4) << 3) + (lane & 7);
                const int g = (kk * 2 + ((lane >> 3) & 1)) ^ (row & 7);
                LDSM_X4(bf[bt], kb + 4u * (uint32_t)(row * 64 + g * 4));
            }
#pragma unroll
            for (int nt = 0; nt < 8; nt++) {
                uint32_t bb[2] = { bf[nt >> 1][(nt & 1) * 2],
                                   bf[nt >> 1][(nt & 1) * 2 + 1] };
                MMA_TF32(sacc[nt], qf[kk], bb);
            }
        }

        // ---- online softmax (rows lane>>2 and lane>>2 + 8) ----
        float mx0 = sacc[0][0], mx1 = sacc[0][2];
#pragma unroll
        for (int nt = 0; nt < 8; nt++) {
            mx0 = fmaxf(mx0, fmaxf(sacc[nt][0], sacc[nt][1]));
            mx1 = fmaxf(mx1, fmaxf(sacc[nt][2], sacc[nt][3]));
        }
        mx0 = fmaxf(mx0, __shfl_xor_sync(0xffffffffu, mx0, 1));
        mx0 = fmaxf(mx0, __shfl_xor_sync(0xffffffffu, mx0, 2));
        mx1 = fmaxf(mx1, __shfl_xor_sync(0xffffffffu, mx1, 1));
        mx1 = fmaxf(mx1, __shfl_xor_sync(0xffffffffu, mx1, 2));

        const float nm0 = fmaxf(m0, mx0);
        const float nm1 = fmaxf(m1, mx1);
        const float c0 = fexp(m0 - nm0);
        const float c1 = fexp(m1 - nm1);
        m0 = nm0; m1 = nm1;
        l0 *= c0;  l1 *= c1;
#pragma unroll
        for (int nd = 0; nd < 8; nd++) {
            oacc[nd][0] *= c0; oacc[nd][1] *= c0;
            oacc[nd][2] *= c1; oacc[nd][3] *= c1;
        }
#pragma unroll
        for (int nt = 0; nt < 8; nt++) {
            const float p0 = fexp(sacc[nt][0] - m0);
            const float p1 = fexp(sacc[nt][1] - m0);
            const float p2 = fexp(sacc[nt][2] - m1);
            const float p3 = fexp(sacc[nt][3] - m1);
            l0 += p0 + p1;
            l1 += p2 + p3;
            sacc[nt][0] = p0; sacc[nt][1] = p1;
            sacc[nt][2] = p2; sacc[nt][3] = p3;
        }

        // ---- O += P @ V  (V^T fragments via ldmatrix) ----
#pragma unroll
        for (int kc = 0; kc < 8; kc++) {
            // P -> A fragment (keys kc*8..+7)
            const uint32_t p0 = cvt_tf32(sacc[kc][0]);
            const uint32_t p1 = cvt_tf32(sacc[kc][1]);
            const uint32_t p2 = cvt_tf32(sacc[kc][2]);
            const uint32_t p3 = cvt_tf32(sacc[kc][3]);
            const int src0 = (lane & 3) >> 1;
            uint32_t a[4], lo, hi;
            lo = __shfl_sync(0xffffffffu, p0, src0, 4);
            hi = __shfl_sync(0xffffffffu, p1, src0, 4);
            a[0] = (lane & 1) ? hi : lo;
            lo = __shfl_sync(0xffffffffu, p2, src0, 4);
            hi = __shfl_sync(0xffffffffu, p3, src0, 4);
            a[1] = (lane & 1) ? hi : lo;
            lo = __shfl_sync(0xffffffffu, p0, src0 + 2, 4);
            hi = __shfl_sync(0xffffffffu, p1, src0 + 2, 4);
            a[2] = (lane & 1) ? hi : lo;
            lo = __shfl_sync(0xffffffffu, p2, src0 + 2, 4);
            hi = __shfl_sync(0xffffffffu, p3, src0 + 2, 4);
            a[3] = (lane & 1) ? hi : lo;

            uint32_t bf[4][4];
#pragma unroll
            for (int bt = 0; bt < 4; bt++) {
                const int row = bt * 16 + ((lane >> 4) << 3) + (lane & 7);   // d row
                const int g = (kc * 2 + ((lane >> 3) & 1)) ^ (row & 7);      // key granule
                LDSM_X4(bf[bt], vb + 4u * (uint32_t)(row * 64 + g * 4));
            }
#pragma unroll
            for (int nd = 0; nd < 8; nd++) {
                uint32_t bb[2] = { bf[nd >> 1][(nd & 1) * 2],
                                   bf[nd >> 1][(nd & 1) * 2 + 1] };
                MMA_TF32(oacc[nd], a, bb);
            }
        }
        __syncthreads();
    }

    // ---- epilogue ----
    l0 += __shfl_xor_sync(0xffffffffu, l0, 1);
    l0 += __shfl_xor_sync(0xffffffffu, l0, 2);
    l1 += __shfl_xor_sync(0xffffffffu, l1, 1);
    l1 += __shfl_xor_sync(0xffffffffu, l1, 2);
    const float i0 = 1.0f / l0;
    const float i1 = 1.0f / l1;
    const int r0 = q0 + w * 16 + (lane >> 2);
#pragma unroll
    for (int nd = 0; nd < 8; nd++) {
        const int c = nd * 8 + (lane & 3) * 2;
        float2 v0 = { oacc[nd][0] * i0, oacc[nd][1] * i0 };
        float2 v1 = { oacc[nd][2] * i1, oacc[nd][3] * i1 };
        *(float2*)(O + base + (size_t)r0 * D + c)       = v0;
        *(float2*)(O + base + (size_t)(r0 + 8) * D + c) = v1;
    }
}

// ---------------- residual + LayerNorm ----------------
__global__ void __launch_bounds__(256) ln_kernel(
    const float* __restrict__ x, const float* __restrict__ y,
    const float* __restrict__ gamma, const float* __restrict__ beta,
    float* __restrict__ out)
{
    __shared__ float red[8];
    const int row = blockIdx.x;
    const int tid = threadIdx.x;

    float4 xv = ((const float4*)(x + (size_t)row * D))[tid];
    float4 yv = ((const float4*)(y + (size_t)row * D))[tid];
    float v[4] = {xv.x + yv.x, xv.y + yv.y, xv.z + yv.z, xv.w + yv.w};

    float s = v[0] + v[1] + v[2] + v[3];
#pragma unroll
    for (int off = 16; off; off >>= 1) s += __shfl_xor_sync(0xffffffffu, s, off);
    if ((tid & 31) == 0) red[tid >> 5] = s;
    __syncthreads();
    if (tid == 0) {
        float t = 0.0f;
        for (int i = 0; i < 8; i++) t += red[i];
        red[0] = t;
    }
    __syncthreads();
    const float mean = red[0] * (1.0f / 1024.0f);
    __syncthreads();

    float ss = 0.0f;
#pragma unroll
    for (int i = 0; i < 4; i++) {
        float d = v[i] - mean;
        ss += d * d;
    }
#pragma unroll
    for (int off = 16; off; off >>= 1) ss += __shfl_xor_sync(0xffffffffu, ss, off);
    if ((tid & 31) == 0) red[tid >> 5] = ss;
    __syncthreads();
    if (tid == 0) {
        float t = 0.0f;
        for (int i = 0; i < 8; i++) t += red[i];
        red[0] = t;
    }
    __syncthreads();
    const float rstd = rsqrtf(red[0] * (1.0f / 1024.0f) + 1e-6f);

    float4 gv = ((const float4*)gamma)[tid];
    float4 bv = ((const float4*)beta)[tid];
    float4 ov;
    ov.x = (v[0] - mean) * rstd * gv.x + bv.x;
    ov.y = (v[1] - mean) * rstd * gv.y + bv.y;
    ov.z = (v[2] - mean) * rstd * gv.z + bv.z;
    ov.w = (v[3] - mean) * rstd * gv.w + bv.w;
    ((float4*)(out + (size_t)row * D))[tid] = ov;
}

// ---------------- launch ----------------
extern "C" void kernel_launch(void* const* d_in, const int* in_sizes, int n_in,
                              void* d_out, int out_size)
{
    const float* x     = (const float*)d_in[0];
    const float* Wq    = (const float*)d_in[1];
    const float* bq    = (const float*)d_in[2];
    const float* Wk    = (const float*)d_in[3];
    const float* bk    = (const float*)d_in[4];
    const float* Wv    = (const float*)d_in[5];
    const float* bv    = (const float*)d_in[6];
    const float* Wo    = (const float*)d_in[7];
    const float* bo    = (const float*)d_in[8];
    const float* gamma = (const float*)d_in[9];
    const float* beta  = (const float*)d_in[10];
    float* out = (float*)d_out;

    float *qp, *kp, *vp, *vtp, *cp, *ap;
    cudaGetSymbolAddress((void**)&qp, g_q);
    cudaGetSymbolAddress((void**)&kp, g_k);
    cudaGetSymbolAddress((void**)&vp, g_v);
    cudaGetSymbolAddress((void**)&vtp, g_vt);
    cudaGetSymbolAddress((void**)&cp, g_ctx);
    cudaGetSymbolAddress((void**)&ap, g_att);

    cudaFuncSetAttribute(gemm_mma, cudaFuncAttributeMaxDynamicSharedMemorySize, GEMM_SMEM);
    cudaFuncSetAttribute(attn_mma, cudaFuncAttributeMaxDynamicSharedMemorySize, ATTN_SMEM);

    dim3 gg(8, 32);
    gemm_mma<<<gg, 256, GEMM_SMEM>>>(x, Wq, bq, qp);
    gemm_mma<<<gg, 256, GEMM_SMEM>>>(x, Wk, bk, kp);
    gemm_mma<<<gg, 256, GEMM_SMEM>>>(x, Wv, bv, vp);
    vtrans<<<dim3(SEQ / 64, H, BAT), 256>>>(vp, vtp);
    attn_mma<<<dim3(SEQ / 128, H, BAT), 256, ATTN_SMEM>>>(qp, kp, vtp, cp);
    gemm_mma<<<gg, 256, GEMM_SMEM>>>(cp, Wo, bo, ap);
    ln_kernel<<<4096, 256>>>(x, ap, gamma, beta, out);
}

// round 6
// speedup vs baseline: 6.6635x; 1.2485x over previous
#include <cuda_runtime.h>
#include <cuda_fp16.h>
#include <cstdint>

#define D   1024
#define SEQ 2048
#define BAT 2
#define H   16
#define HD  64
#define TOK (BAT * SEQ)   // 4096

// ---------------- scratch (no allocations allowed) ----------------
__device__ float  g_q[TOK * D];
__device__ float  g_k[TOK * D];
__device__ float  g_v[TOK * D];
__device__ __half g_vh[TOK * D];    // fp16 copy of V, written by V-GEMM epilogue
__device__ float  g_ctx[TOK * D];
__device__ float  g_att[TOK * D];

// ==================== helpers ====================
__device__ __forceinline__ uint32_t smem_u32(const void* p) {
    uint32_t a;
    asm("{ .reg .u64 t; cvta.to.shared.u64 t, %1; cvt.u32.u64 %0, t; }" : "=r"(a) : "l"(p));
    return a;
}

__device__ __forceinline__ uint32_t packh2(float lo, float hi) {
    uint32_t u;
    asm("cvt.rn.f16x2.f32 %0, %1, %2;" : "=r"(u) : "f"(hi), "f"(lo));
    return u;
}

#define LDSM_X4(r, addr) \
    asm volatile("ldmatrix.sync.aligned.m8n8.x4.shared.b16 {%0,%1,%2,%3}, [%4];" \
                 : "=r"((r)[0]), "=r"((r)[1]), "=r"((r)[2]), "=r"((r)[3]) : "r"(addr))

#define LDSM_X4T(r, addr) \
    asm volatile("ldmatrix.sync.aligned.m8n8.x4.trans.shared.b16 {%0,%1,%2,%3}, [%4];" \
                 : "=r"((r)[0]), "=r"((r)[1]), "=r"((r)[2]), "=r"((r)[3]) : "r"(addr))

#define MMA_TF32(acc, a, b) \
    asm volatile("mma.sync.aligned.m16n8k8.row.col.f32.tf32.tf32.f32 " \
                 "{%0,%1,%2,%3}, {%4,%5,%6,%7}, {%8,%9}, {%0,%1,%2,%3};" \
                 : "+f"((acc)[0]), "+f"((acc)[1]), "+f"((acc)[2]), "+f"((acc)[3]) \
                 : "r"((a)[0]), "r"((a)[1]), "r"((a)[2]), "r"((a)[3]), \
                   "r"((b)[0]), "r"((b)[1]))

#define MMA_F16(acc, a, b) \
    asm volatile("mma.sync.aligned.m16n8k16.row.col.f32.f16.f16.f32 " \
                 "{%0,%1,%2,%3}, {%4,%5,%6,%7}, {%8,%9}, {%0,%1,%2,%3};" \
                 : "+f"((acc)[0]), "+f"((acc)[1]), "+f"((acc)[2]), "+f"((acc)[3]) \
                 : "r"((a)[0]), "r"((a)[1]), "r"((a)[2]), "r"((a)[3]), \
                   "r"((b)[0]), "r"((b)[1]))

#define CP_ASYNC16(smem, gmem) \
    asm volatile("cp.async.ca.shared.global [%0], [%1], 16;" :: "r"(smem), "l"(gmem) : "memory")
#define CP_COMMIT asm volatile("cp.async.commit_group;" ::: "memory")
#define CP_WAIT1  asm volatile("cp.async.wait_group 1;" ::: "memory")
#define CP_WAIT0  asm volatile("cp.async.wait_group 0;" ::: "memory")

// ---------------- fast exp on FMA pipe ----------------
__device__ __forceinline__ float fexp(float x) {
    float t = fmaxf(x * 1.4426950408889634f, -125.0f);
    float fi = floorf(t);
    float f  = t - fi;
    float r  = 0.0013333558f;
    r = r * f + 0.0096181291f;
    r = r * f + 0.0555041086f;
    r = r * f + 0.2402265069f;
    r = r * f + 0.6931471806f;
    r = r * f + 1.0f;
    int e = (int)fi;
    return __int_as_float((e + 127) << 23) * r;
}

// ==================== cp.async 3-stage tf32 GEMM ====================
// C[4096,1024] = A @ W^T + bias.  BM=BN=128, BK=32, 8 warps, 3-stage cp.async.
// blockIdx.z selects among up to 3 (W, bias, C) sets sharing the same A.
// smem: 3 stages x (A 16KB | B 16KB) = 96KB, raw fp32 (HMMA.TF32 truncates).
#define GEMM_SMEM 98304

struct GArgs {
    const float *A, *W0, *W1, *W2, *b0, *b1, *b2;
    float *C0, *C1, *C2;
    __half *Ch2;   // optional fp16 mirror for z==2 output
};

__global__ void __launch_bounds__(256) gemm_mma(GArgs ga)
{
    extern __shared__ float sm[];
    const uint32_t smb = smem_u32(sm);

    const int z = blockIdx.z;
    const float* A    = ga.A;
    const float* W    = (z == 0) ? ga.W0 : (z == 1) ? ga.W1 : ga.W2;
    const float* bias = (z == 0) ? ga.b0 : (z == 1) ? ga.b1 : ga.b2;
    float*       C    = (z == 0) ? ga.C0 : (z == 1) ? ga.C1 : ga.C2;
    __half*      Ch   = (z == 2) ? ga.Ch2 : nullptr;

    const int tid  = threadIdx.x;
    const int lane = tid & 31;
    const int wid  = tid >> 5;
    const int wm   = (wid >> 2) * 64;
    const int wn   = (wid & 3) * 32;
    const int bm   = blockIdx.y * 128;
    const int bn   = blockIdx.x * 128;

    float acc[4][4][4];
#pragma unroll
    for (int mt = 0; mt < 4; mt++)
#pragma unroll
        for (int nt = 0; nt < 4; nt++)
#pragma unroll
            for (int r = 0; r < 4; r++) acc[mt][nt][r] = 0.0f;

    auto stage = [&](int c, int buf) {
        const uint32_t sb = smb + (uint32_t)buf * 32768u;
        const int k0 = c * 32;
#pragma unroll
        for (int i = 0; i < 4; i++) {
            const int lin = tid + i * 256;
            const int r = lin >> 3, gg = lin & 7;
            const uint32_t off = (uint32_t)(r * 128 + ((gg ^ (r & 7)) << 4));
            CP_ASYNC16(sb + off, A + (size_t)(bm + r) * 1024 + k0 + gg * 4);
            CP_ASYNC16(sb + 16384u + off, W + (size_t)(bn + r) * 1024 + k0 + gg * 4);
        }
    };

    stage(0, 0); CP_COMMIT;
    stage(1, 1); CP_COMMIT;

    for (int c = 0; c < 32; c++) {
        if (c < 31) { CP_WAIT1; } else { CP_WAIT0; }
        __syncthreads();
        if (c + 2 < 32) { stage(c + 2, (c + 2) % 3); CP_COMMIT; }

        const uint32_t a_base = smb + (uint32_t)(c % 3) * 32768u;
        const uint32_t b_base = a_base + 16384u;

#pragma unroll
        for (int kk8 = 0; kk8 < 4; kk8++) {
            uint32_t af[4][4];
#pragma unroll
            for (int mt = 0; mt < 4; mt++) {
                const int row = wm + mt * 16 + (lane & 15);
                const int g = (kk8 * 2 + (lane >> 4)) ^ (row & 7);
                LDSM_X4(af[mt], a_base + (uint32_t)(row * 128 + g * 16));
            }
            uint32_t bf[2][4];
#pragma unroll
            for (int bt = 0; bt < 2; bt++) {
                const int row = wn + bt * 16 + ((lane >> 4) << 3) + (lane & 7);
                const int g = (kk8 * 2 + ((lane >> 3) & 1)) ^ (row & 7);
                LDSM_X4(bf[bt], b_base + (uint32_t)(row * 128 + g * 16));
            }
#pragma unroll
            for (int mt = 0; mt < 4; mt++)
#pragma unroll
                for (int nt = 0; nt < 4; nt++) {
                    uint32_t bb[2] = { bf[nt >> 1][(nt & 1) * 2],
                                       bf[nt >> 1][(nt & 1) * 2 + 1] };
                    MMA_TF32(acc[mt][nt], af[mt], bb);
                }
        }
        __syncthreads();
    }

#pragma unroll
    for (int mt = 0; mt < 4; mt++) {
        const int r0 = bm + wm + mt * 16 + (lane >> 2);
#pragma unroll
        for (int nt = 0; nt < 4; nt++) {
            const int c0 = bn + wn + nt * 8 + ((lane & 3) << 1);
            const float2 bb = *(const float2*)(bias + c0);
            float2 o0 = { acc[mt][nt][0] + bb.x, acc[mt][nt][1] + bb.y };
            float2 o1 = { acc[mt][nt][2] + bb.x, acc[mt][nt][3] + bb.y };
            *(float2*)(C + (size_t)r0 * 1024 + c0)       = o0;
            *(float2*)(C + (size_t)(r0 + 8) * 1024 + c0) = o1;
            if (Ch) {
                *(uint32_t*)(Ch + (size_t)r0 * 1024 + c0)       = packh2(o0.x, o0.y);
                *(uint32_t*)(Ch + (size_t)(r0 + 8) * 1024 + c0) = packh2(o1.x, o1.y);
            }
        }
    }
}

// ==================== flash attention: tf32 QK^T + fp16 PV ====================
// CTA: 128 q rows, 8 warps (16 each). K tiles fp32 (tf32-truncated), V tiles fp16.
// smem bytes: Q [0,32768) | K0 [32768,49152) | K1 [49152,65536)
//           | V0 [65536,73728) | V1 [73728,81920)
#define ATTN_SMEM 81920

__global__ void __launch_bounds__(256) attn_mma(
    const float* __restrict__ Q, const float* __restrict__ K,
    const __half* __restrict__ Vh, float* __restrict__ O)
{
    extern __shared__ float smf[];
    const uint32_t smb = smem_u32(smf);

    const int tid  = threadIdx.x;
    const int lane = tid & 31;
    const int w    = tid >> 5;
    const int q0   = blockIdx.x * 128;
    const int h    = blockIdx.y;
    const int b    = blockIdx.z;
    const size_t base = (size_t)b * SEQ * D + (size_t)h * HD;

    // ---- stage Q (scale folded, raw fp32), swizzled 256B rows ----
#pragma unroll
    for (int j = 0; j < 8; j++) {
        const int idx = tid + j * 256;
        const int r = idx >> 4, g = idx & 15;
        float4 t = *(const float4*)(Q + base + (size_t)(q0 + r) * D + g * 4);
        float4 s = { t.x * 0.125f, t.y * 0.125f, t.z * 0.125f, t.w * 0.125f };
        *(float4*)((char*)smf + r * 256 + ((g ^ (r & 7)) << 4)) = s;
    }

    // ---- stage K/V tile 0 (cp.async) ----
#pragma unroll
    for (int j = 0; j < 4; j++) {
        const int idx = tid + j * 256;
        const int r = idx >> 4, g = idx & 15;
        CP_ASYNC16(smb + 32768u + (uint32_t)(r * 256 + ((g ^ (r & 7)) << 4)),
                   K + base + (size_t)r * D + g * 4);
    }
#pragma unroll
    for (int j = 0; j < 2; j++) {
        const int idx = tid + j * 256;
        const int s = idx >> 3, sg = idx & 7;
        CP_ASYNC16(smb + 65536u + (uint32_t)(s * 128 + ((sg ^ (s & 7)) << 4)),
                   Vh + base + (size_t)s * D + sg * 8);
    }
    CP_COMMIT;
    __syncthreads();

    // ---- load Q fragments once ----
    uint32_t qf[8][4];
#pragma unroll
    for (int kk = 0; kk < 8; kk++) {
        const int row = w * 16 + (lane & 15);
        const int g = (kk * 2 + (lane >> 4)) ^ (row & 7);
        LDSM_X4(qf[kk], smb + (uint32_t)(row * 256 + g * 16));
    }

    float m0 = -1e30f, m1 = -1e30f, l0 = 0.0f, l1 = 0.0f;
    float oacc[8][4];
#pragma unroll
    for (int nd = 0; nd < 8; nd++)
#pragma unroll
        for (int r = 0; r < 4; r++) oacc[nd][r] = 0.0f;

    const int vt   = lane & 7;
    const int vq   = lane >> 3;

    for (int it = 0; it < SEQ / 64; it++) {
        const int buf = it & 1;
        if (it + 1 < SEQ / 64) {
            const int kt = it + 1;
            const uint32_t kb2 = smb + 32768u + (uint32_t)(buf ^ 1) * 16384u;
            const uint32_t vb2 = smb + 65536u + (uint32_t)(buf ^ 1) * 8192u;
#pragma unroll
            for (int j = 0; j < 4; j++) {
                const int idx = tid + j * 256;
                const int r = idx >> 4, g = idx & 15;
                CP_ASYNC16(kb2 + (uint32_t)(r * 256 + ((g ^ (r & 7)) << 4)),
                           K + base + (size_t)(kt * 64 + r) * D + g * 4);
            }
#pragma unroll
            for (int j = 0; j < 2; j++) {
                const int idx = tid + j * 256;
                const int s = idx >> 3, sg = idx & 7;
                CP_ASYNC16(vb2 + (uint32_t)(s * 128 + ((sg ^ (s & 7)) << 4)),
                           Vh + base + (size_t)(kt * 64 + s) * D + sg * 8);
            }
            CP_COMMIT;
            CP_WAIT1;
        } else {
            CP_WAIT0;
        }
        __syncthreads();

        const uint32_t kb = smb + 32768u + (uint32_t)buf * 16384u;
        const uint32_t vb = smb + 65536u + (uint32_t)buf * 8192u;

        // ---- S = Q @ K^T (16 x 64 per warp) ----
        float sacc[8][4];
#pragma unroll
        for (int nt = 0; nt < 8; nt++)
#pragma unroll
            for (int r = 0; r < 4; r++) sacc[nt][r] = 0.0f;

#pragma unroll
        for (int kk = 0; kk < 8; kk++) {
            uint32_t bf[4][4];
#pragma unroll
            for (int bt = 0; bt < 4; bt++) {
                const int row = bt * 16 + ((lane >> 4) << 3) + (lane & 7);
                const int g = (kk * 2 + ((lane >> 3) & 1)) ^ (row & 7);
                LDSM_X4(bf[bt], kb + (uint32_t)(row * 256 + g * 16));
            }
#pragma unroll
            for (int nt = 0; nt < 8; nt++) {
                uint32_t bb[2] = { bf[nt >> 1][(nt & 1) * 2],
                                   bf[nt >> 1][(nt & 1) * 2 + 1] };
                MMA_TF32(sacc[nt], qf[kk], bb);
            }
        }

        // ---- online softmax ----
        float mx0 = sacc[0][0], mx1 = sacc[0][2];
#pragma unroll
        for (int nt = 0; nt < 8; nt++) {
            mx0 = fmaxf(mx0, fmaxf(sacc[nt][0], sacc[nt][1]));
            mx1 = fmaxf(mx1, fmaxf(sacc[nt][2], sacc[nt][3]));
        }
        mx0 = fmaxf(mx0, __shfl_xor_sync(0xffffffffu, mx0, 1));
        mx0 = fmaxf(mx0, __shfl_xor_sync(0xffffffffu, mx0, 2));
        mx1 = fmaxf(mx1, __shfl_xor_sync(0xffffffffu, mx1, 1));
        mx1 = fmaxf(mx1, __shfl_xor_sync(0xffffffffu, mx1, 2));

        const float nm0 = fmaxf(m0, mx0);
        const float nm1 = fmaxf(m1, mx1);
        const float c0 = fexp(m0 - nm0);
        const float c1 = fexp(m1 - nm1);
        m0 = nm0; m1 = nm1;
        l0 *= c0;  l1 *= c1;
#pragma unroll
        for (int nd = 0; nd < 8; nd++) {
            oacc[nd][0] *= c0; oacc[nd][1] *= c0;
            oacc[nd][2] *= c1; oacc[nd][3] *= c1;
        }
#pragma unroll
        for (int nt = 0; nt < 8; nt++) {
            const float p0 = fexp(sacc[nt][0] - m0);
            const float p1 = fexp(sacc[nt][1] - m0);
            const float p2 = fexp(sacc[nt][2] - m1);
            const float p3 = fexp(sacc[nt][3] - m1);
            l0 += p0 + p1;
            l1 += p2 + p3;
            sacc[nt][0] = p0; sacc[nt][1] = p1;
            sacc[nt][2] = p2; sacc[nt][3] = p3;
        }

        // ---- O += P @ V  (fp16, zero shuffles) ----
#pragma unroll
        for (int kc = 0; kc < 4; kc++) {
            uint32_t a[4];
            a[0] = packh2(sacc[2 * kc][0],     sacc[2 * kc][1]);
            a[1] = packh2(sacc[2 * kc][2],     sacc[2 * kc][3]);
            a[2] = packh2(sacc[2 * kc + 1][0], sacc[2 * kc + 1][1]);
            a[3] = packh2(sacc[2 * kc + 1][2], sacc[2 * kc + 1][3]);

            const int row = kc * 16 + ((vq & 1) << 3) + vt;
#pragma unroll
            for (int dn = 0; dn < 4; dn++) {
                const int seg = dn * 2 + (vq >> 1);
                uint32_t r4[4];
                LDSM_X4T(r4, vb + (uint32_t)(row * 128 + ((seg ^ (row & 7)) << 4)));
                MMA_F16(oacc[dn * 2],     a, r4);
                MMA_F16(oacc[dn * 2 + 1], a, (r4 + 2));
            }
        }
        __syncthreads();
    }

    // ---- epilogue ----
    l0 += __shfl_xor_sync(0xffffffffu, l0, 1);
    l0 += __shfl_xor_sync(0xffffffffu, l0, 2);
    l1 += __shfl_xor_sync(0xffffffffu, l1, 1);
    l1 += __shfl_xor_sync(0xffffffffu, l1, 2);
    const float i0 = 1.0f / l0;
    const float i1 = 1.0f / l1;
    const int r0 = q0 + w * 16 + (lane >> 2);
#pragma unroll
    for (int nd = 0; nd < 8; nd++) {
        const int c = nd * 8 + (lane & 3) * 2;
        float2 v0 = { oacc[nd][0] * i0, oacc[nd][1] * i0 };
        float2 v1 = { oacc[nd][2] * i1, oacc[nd][3] * i1 };
        *(float2*)(O + base + (size_t)r0 * D + c)       = v0;
        *(float2*)(O + base + (size_t)(r0 + 8) * D + c) = v1;
    }
}

// ---------------- residual + LayerNorm ----------------
__global__ void __launch_bounds__(256) ln_kernel(
    const float* __restrict__ x, const float* __restrict__ y,
    const float* __restrict__ gamma, const float* __restrict__ beta,
    float* __restrict__ out)
{
    __shared__ float red[8];
    const int row = blockIdx.x;
    const int tid = threadIdx.x;

    float4 xv = ((const float4*)(x + (size_t)row * D))[tid];
    float4 yv = ((const float4*)(y + (size_t)row * D))[tid];
    float v[4] = {xv.x + yv.x, xv.y + yv.y, xv.z + yv.z, xv.w + yv.w};

    float s = v[0] + v[1] + v[2] + v[3];
#pragma unroll
    for (int off = 16; off; off >>= 1) s += __shfl_xor_sync(0xffffffffu, s, off);
    if ((tid & 31) == 0) red[tid >> 5] = s;
    __syncthreads();
    if (tid == 0) {
        float t = 0.0f;
        for (int i = 0; i < 8; i++) t += red[i];
        red[0] = t;
    }
    __syncthreads();
    const float mean = red[0] * (1.0f / 1024.0f);
    __syncthreads();

    float ss = 0.0f;
#pragma unroll
    for (int i = 0; i < 4; i++) {
        float d = v[i] - mean;
        ss += d * d;
    }
#pragma unroll
    for (int off = 16; off; off >>= 1) ss += __shfl_xor_sync(0xffffffffu, ss, off);
    if ((tid & 31) == 0) red[tid >> 5] = ss;
    __syncthreads();
    if (tid == 0) {
        float t = 0.0f;
        for (int i = 0; i < 8; i++) t += red[i];
        red[0] = t;
    }
    __syncthreads();
    const float rstd = rsqrtf(red[0] * (1.0f / 1024.0f) + 1e-6f);

    float4 gv = ((const float4*)gamma)[tid];
    float4 bv = ((const float4*)beta)[tid];
    float4 ov;
    ov.x = (v[0] - mean) * rstd * gv.x + bv.x;
    ov.y = (v[1] - mean) * rstd * gv.y + bv.y;
    ov.z = (v[2] - mean) * rstd * gv.z + bv.z;
    ov.w = (v[3] - mean) * rstd * gv.w + bv.w;
    ((float4*)(out + (size_t)row * D))[tid] = ov;
}

// ---------------- launch ----------------
extern "C" void kernel_launch(void* const* d_in, const int* in_sizes, int n_in,
                              void* d_out, int out_size)
{
    const float* x     = (const float*)d_in[0];
    const float* Wq    = (const float*)d_in[1];
    const float* bq    = (const float*)d_in[2];
    const float* Wk    = (const float*)d_in[3];
    const float* bk    = (const float*)d_in[4];
    const float* Wv    = (const float*)d_in[5];
    const float* bv    = (const float*)d_in[6];
    const float* Wo    = (const float*)d_in[7];
    const float* bo    = (const float*)d_in[8];
    const float* gamma = (const float*)d_in[9];
    const float* beta  = (const float*)d_in[10];
    float* out = (float*)d_out;

    float *qp, *kp, *vp, *cp, *ap;
    __half* vhp;
    cudaGetSymbolAddress((void**)&qp, g_q);
    cudaGetSymbolAddress((void**)&kp, g_k);
    cudaGetSymbolAddress((void**)&vp, g_v);
    cudaGetSymbolAddress((void**)&vhp, g_vh);
    cudaGetSymbolAddress((void**)&cp, g_ctx);
    cudaGetSymbolAddress((void**)&ap, g_att);

    cudaFuncSetAttribute(gemm_mma, cudaFuncAttributeMaxDynamicSharedMemorySize, GEMM_SMEM);
    cudaFuncSetAttribute(attn_mma, cudaFuncAttributeMaxDynamicSharedMemorySize, ATTN_SMEM);

    GArgs qkv = { x, Wq, Wk, Wv, bq, bk, bv, qp, kp, vp, vhp };
    gemm_mma<<<dim3(8, 32, 3), 256, GEMM_SMEM>>>(qkv);

    attn_mma<<<dim3(SEQ / 128, H, BAT), 256, ATTN_SMEM>>>(qp, kp, vhp, cp);

    GArgs oproj = { cp, Wo, Wo, Wo, bo, bo, bo, ap, ap, ap, nullptr };
    gemm_mma<<<dim3(8, 32, 1), 256, GEMM_SMEM>>>(oproj);

    ln_kernel<<<4096, 256>>>(x, ap, gamma, beta, out);
}

// round 7
// speedup vs baseline: 9.6300x; 1.4452x over previous
#include <cuda_runtime.h>
#include <cuda_fp16.h>
#include <cstdint>

#define D   1024
#define SEQ 2048
#define BAT 2
#define H   16
#define HD  64
#define TOK (BAT * SEQ)   // 4096

// ---------------- scratch (no allocations allowed) ----------------
__device__ __half g_xh[TOK * D];
__device__ __half g_wqh[D * D];
__device__ __half g_wkh[D * D];
__device__ __half g_wvh[D * D];
__device__ __half g_woh[D * D];
__device__ __half g_qh[TOK * D];
__device__ __half g_kh[TOK * D];
__device__ __half g_vh[TOK * D];
__device__ __half g_ch[TOK * D];   // ctx fp16
__device__ float  g_att[TOK * D];

// ==================== helpers ====================
__device__ __forceinline__ uint32_t smem_u32(const void* p) {
    uint32_t a;
    asm("{ .reg .u64 t; cvta.to.shared.u64 t, %1; cvt.u32.u64 %0, t; }" : "=r"(a) : "l"(p));
    return a;
}

__device__ __forceinline__ uint32_t packh2(float lo, float hi) {
    uint32_t u;
    asm("cvt.rn.f16x2.f32 %0, %1, %2;" : "=r"(u) : "f"(hi), "f"(lo));
    return u;
}

#define LDSM_X4(r, addr) \
    asm volatile("ldmatrix.sync.aligned.m8n8.x4.shared.b16 {%0,%1,%2,%3}, [%4];" \
                 : "=r"((r)[0]), "=r"((r)[1]), "=r"((r)[2]), "=r"((r)[3]) : "r"(addr))

#define LDSM_X4T(r, addr) \
    asm volatile("ldmatrix.sync.aligned.m8n8.x4.trans.shared.b16 {%0,%1,%2,%3}, [%4];" \
                 : "=r"((r)[0]), "=r"((r)[1]), "=r"((r)[2]), "=r"((r)[3]) : "r"(addr))

#define MMA_F16(acc, a, b) \
    asm volatile("mma.sync.aligned.m16n8k16.row.col.f32.f16.f16.f32 " \
                 "{%0,%1,%2,%3}, {%4,%5,%6,%7}, {%8,%9}, {%0,%1,%2,%3};" \
                 : "+f"((acc)[0]), "+f"((acc)[1]), "+f"((acc)[2]), "+f"((acc)[3]) \
                 : "r"((a)[0]), "r"((a)[1]), "r"((a)[2]), "r"((a)[3]), \
                   "r"((b)[0]), "r"((b)[1]))

#define CP_ASYNC16(smem, gmem) \
    asm volatile("cp.async.ca.shared.global [%0], [%1], 16;" :: "r"(smem), "l"(gmem) : "memory")
#define CP_COMMIT asm volatile("cp.async.commit_group;" ::: "memory")
#define CP_WAIT1  asm volatile("cp.async.wait_group 1;" ::: "memory")
#define CP_WAIT0  asm volatile("cp.async.wait_group 0;" ::: "memory")

// ---------------- fast exp on FMA pipe ----------------
__device__ __forceinline__ float fexp(float x) {
    float t = fmaxf(x * 1.4426950408889634f, -125.0f);
    float fi = floorf(t);
    float f  = t - fi;
    float r  = 0.0013333558f;
    r = r * f + 0.0096181291f;
    r = r * f + 0.0555041086f;
    r = r * f + 0.2402265069f;
    r = r * f + 0.6931471806f;
    r = r * f + 1.0f;
    int e = (int)fi;
    return __int_as_float((e + 127) << 23) * r;
}

// ==================== fp32 -> fp16 convert ====================
__global__ void __launch_bounds__(256) to_half(
    const float* __restrict__ src, __half* __restrict__ dst, int n)
{
    const int i = (blockIdx.x * 256 + threadIdx.x) * 4;
    if (i < n) {
        float4 v = *(const float4*)(src + i);
        uint2 o = { packh2(v.x, v.y), packh2(v.z, v.w) };
        *(uint2*)(dst + i) = o;
    }
}

// ==================== cp.async 3-stage fp16 GEMM ====================
// C[4096,1024] = A @ W^T + bias.  BM=BN=128, BK=64, 8 warps, 3-stage cp.async.
// smem: 3 stages x (A 16KB | B 16KB) = 96KB.
#define GEMM_SMEM 98304

struct GArgs {
    const __half* A;
    const __half* W[3];
    const float*  b[3];
    float*        Cf[3];   // fp32 out (nullable)
    __half*       Ch[3];   // fp16 out (nullable)
};

__global__ void __launch_bounds__(256) gemm_mma(GArgs ga)
{
    extern __shared__ char smch[];
    const uint32_t smb = smem_u32(smch);

    const int z = blockIdx.z;
    const __half* A    = ga.A;
    const __half* W    = ga.W[z];
    const float*  bias = ga.b[z];
    float*        Cf   = ga.Cf[z];
    __half*       Ch   = ga.Ch[z];

    const int tid  = threadIdx.x;
    const int lane = tid & 31;
    const int wid  = tid >> 5;
    const int wm   = (wid >> 2) * 64;
    const int wn   = (wid & 3) * 32;
    const int bm   = blockIdx.y * 128;
    const int bn   = blockIdx.x * 128;

    float acc[4][4][4];
#pragma unroll
    for (int mt = 0; mt < 4; mt++)
#pragma unroll
        for (int nt = 0; nt < 4; nt++)
#pragma unroll
            for (int r = 0; r < 4; r++) acc[mt][nt][r] = 0.0f;

    auto stage = [&](int c, int buf) {
        const uint32_t sb = smb + (uint32_t)buf * 32768u;
        const int k0 = c * 64;
#pragma unroll
        for (int i = 0; i < 4; i++) {
            const int lin = tid + i * 256;
            const int r = lin >> 3, gg = lin & 7;
            const uint32_t off = (uint32_t)(r * 128 + ((gg ^ (r & 7)) << 4));
            CP_ASYNC16(sb + off, A + (size_t)(bm + r) * 1024 + k0 + gg * 8);
            CP_ASYNC16(sb + 16384u + off, W + (size_t)(bn + r) * 1024 + k0 + gg * 8);
        }
    };

    stage(0, 0); CP_COMMIT;
    stage(1, 1); CP_COMMIT;

    for (int c = 0; c < 16; c++) {
        if (c < 15) { CP_WAIT1; } else { CP_WAIT0; }
        __syncthreads();
        if (c + 2 < 16) { stage(c + 2, (c + 2) % 3); CP_COMMIT; }

        const uint32_t a_base = smb + (uint32_t)(c % 3) * 32768u;
        const uint32_t b_base = a_base + 16384u;

#pragma unroll
        for (int kk = 0; kk < 4; kk++) {   // 4 x k16 = 64
            uint32_t af[4][4];
#pragma unroll
            for (int mt = 0; mt < 4; mt++) {
                const int row = wm + mt * 16 + (lane & 15);
                const int g = (kk * 2 + (lane >> 4)) ^ (row & 7);
                LDSM_X4(af[mt], a_base + (uint32_t)(row * 128 + g * 16));
            }
            uint32_t bf[2][4];
#pragma unroll
            for (int bt = 0; bt < 2; bt++) {
                const int row = wn + bt * 16 + ((lane >> 4) << 3) + (lane & 7);
                const int g = (kk * 2 + ((lane >> 3) & 1)) ^ (row & 7);
                LDSM_X4(bf[bt], b_base + (uint32_t)(row * 128 + g * 16));
            }
#pragma unroll
            for (int mt = 0; mt < 4; mt++)
#pragma unroll
                for (int nt = 0; nt < 4; nt++) {
                    uint32_t bb[2] = { bf[nt >> 1][(nt & 1) * 2],
                                       bf[nt >> 1][(nt & 1) * 2 + 1] };
                    MMA_F16(acc[mt][nt], af[mt], bb);
                }
        }
        __syncthreads();
    }

#pragma unroll
    for (int mt = 0; mt < 4; mt++) {
        const int r0 = bm + wm + mt * 16 + (lane >> 2);
#pragma unroll
        for (int nt = 0; nt < 4; nt++) {
            const int c0 = bn + wn + nt * 8 + ((lane & 3) << 1);
            const float2 bb = *(const float2*)(bias + c0);
            float2 o0 = { acc[mt][nt][0] + bb.x, acc[mt][nt][1] + bb.y };
            float2 o1 = { acc[mt][nt][2] + bb.x, acc[mt][nt][3] + bb.y };
            if (Cf) {
                *(float2*)(Cf + (size_t)r0 * 1024 + c0)       = o0;
                *(float2*)(Cf + (size_t)(r0 + 8) * 1024 + c0) = o1;
            }
            if (Ch) {
                *(uint32_t*)(Ch + (size_t)r0 * 1024 + c0)       = packh2(o0.x, o0.y);
                *(uint32_t*)(Ch + (size_t)(r0 + 8) * 1024 + c0) = packh2(o1.x, o1.y);
            }
        }
    }
}

// ==================== fp16 flash attention ====================
// CTA: 128 q rows, 8 warps (16 each). K/V tiles of 64 keys, double buffered.
// smem bytes: Q [0,16384) | K0 [16384,24576) | K1 [24576,32768)
//           | V0 [32768,40960) | V1 [40960,49152)
#define ATTN_SMEM 49152

__global__ void __launch_bounds__(256) attn_mma(
    const __half* __restrict__ Qh, const __half* __restrict__ Kh,
    const __half* __restrict__ Vh, __half* __restrict__ Oh)
{
    extern __shared__ char smch[];
    const uint32_t smb = smem_u32(smch);

    const int tid  = threadIdx.x;
    const int lane = tid & 31;
    const int w    = tid >> 5;
    const int q0   = blockIdx.x * 128;
    const int h    = blockIdx.y;
    const int b    = blockIdx.z;
    const size_t base = (size_t)b * SEQ * D + (size_t)h * HD;

    // ---- stage Q (scale 0.125 folded — exact in fp16) ----
    {
        const __half2 sc = __half2half2(__float2half(0.125f));
#pragma unroll
        for (int j = 0; j < 4; j++) {
            const int idx = tid + j * 256;
            const int r = idx >> 3, g = idx & 7;
            uint2 v = *(const uint2*)(Qh + base + (size_t)(q0 + r) * D + g * 8);
            __half2 h0 = __hmul2(*(__half2*)&v.x, sc);
            __half2 h1 = __hmul2(*(__half2*)&v.y, sc);
            uint2 vv = *(const uint2*)(Qh + base + (size_t)(q0 + r) * D + g * 8 + 4);
            __half2 h2 = __hmul2(*(__half2*)&vv.x, sc);
            __half2 h3 = __hmul2(*(__half2*)&vv.y, sc);
            uint4 o = { *(uint32_t*)&h0, *(uint32_t*)&h1, *(uint32_t*)&h2, *(uint32_t*)&h3 };
            *(uint4*)(smch + r * 128 + ((g ^ (r & 7)) << 4)) = o;
        }
    }

    // ---- stage K/V tile 0 (cp.async) ----
#pragma unroll
    for (int j = 0; j < 2; j++) {
        const int idx = tid + j * 256;
        const int r = idx >> 3, g = idx & 7;
        const uint32_t off = (uint32_t)(r * 128 + ((g ^ (r & 7)) << 4));
        CP_ASYNC16(smb + 16384u + off, Kh + base + (size_t)r * D + g * 8);
        CP_ASYNC16(smb + 32768u + off, Vh + base + (size_t)r * D + g * 8);
    }
    CP_COMMIT;
    __syncthreads();

    // ---- load Q fragments once (4 k16 steps) ----
    uint32_t qf[4][4];
#pragma unroll
    for (int kk = 0; kk < 4; kk++) {
        const int row = w * 16 + (lane & 15);
        const int g = (kk * 2 + (lane >> 4)) ^ (row & 7);
        LDSM_X4(qf[kk], smb + (uint32_t)(row * 128 + g * 16));
    }

    float m0 = -1e30f, m1 = -1e30f, l0 = 0.0f, l1 = 0.0f;
    float oacc[8][4];
#pragma unroll
    for (int nd = 0; nd < 8; nd++)
#pragma unroll
        for (int r = 0; r < 4; r++) oacc[nd][r] = 0.0f;

    const int vt = lane & 7;
    const int vq = lane >> 3;

    for (int it = 0; it < SEQ / 64; it++) {
        const int buf = it & 1;
        if (it + 1 < SEQ / 64) {
            const int kt = it + 1;
            const uint32_t kb2 = smb + 16384u + (uint32_t)(buf ^ 1) * 8192u;
            const uint32_t vb2 = smb + 32768u + (uint32_t)(buf ^ 1) * 8192u;
#pragma unroll
            for (int j = 0; j < 2; j++) {
                const int idx = tid + j * 256;
                const int r = idx >> 3, g = idx & 7;
                const uint32_t off = (uint32_t)(r * 128 + ((g ^ (r & 7)) << 4));
                CP_ASYNC16(kb2 + off, Kh + base + (size_t)(kt * 64 + r) * D + g * 8);
                CP_ASYNC16(vb2 + off, Vh + base + (size_t)(kt * 64 + r) * D + g * 8);
            }
            CP_COMMIT;
            CP_WAIT1;
        } else {
            CP_WAIT0;
        }
        __syncthreads();

        const uint32_t kb = smb + 16384u + (uint32_t)buf * 8192u;
        const uint32_t vb = smb + 32768u + (uint32_t)buf * 8192u;

        // ---- S = Q @ K^T (16 x 64 per warp, fp16) ----
        float sacc[8][4];
#pragma unroll
        for (int nt = 0; nt < 8; nt++)
#pragma unroll
            for (int r = 0; r < 4; r++) sacc[nt][r] = 0.0f;

#pragma unroll
        for (int kk = 0; kk < 4; kk++) {
            uint32_t bf[4][4];
#pragma unroll
            for (int bt = 0; bt < 4; bt++) {
                const int row = bt * 16 + ((lane >> 4) << 3) + (lane & 7);
                const int g = (kk * 2 + ((lane >> 3) & 1)) ^ (row & 7);
                LDSM_X4(bf[bt], kb + (uint32_t)(row * 128 + g * 16));
            }
#pragma unroll
            for (int nt = 0; nt < 8; nt++) {
                uint32_t bb[2] = { bf[nt >> 1][(nt & 1) * 2],
                                   bf[nt >> 1][(nt & 1) * 2 + 1] };
                MMA_F16(sacc[nt], qf[kk], bb);
            }
        }

        // ---- online softmax ----
        float mx0 = sacc[0][0], mx1 = sacc[0][2];
#pragma unroll
        for (int nt = 0; nt < 8; nt++) {
            mx0 = fmaxf(mx0, fmaxf(sacc[nt][0], sacc[nt][1]));
            mx1 = fmaxf(mx1, fmaxf(sacc[nt][2], sacc[nt][3]));
        }
        mx0 = fmaxf(mx0, __shfl_xor_sync(0xffffffffu, mx0, 1));
        mx0 = fmaxf(mx0, __shfl_xor_sync(0xffffffffu, mx0, 2));
        mx1 = fmaxf(mx1, __shfl_xor_sync(0xffffffffu, mx1, 1));
        mx1 = fmaxf(mx1, __shfl_xor_sync(0xffffffffu, mx1, 2));

        const float nm0 = fmaxf(m0, mx0);
        const float nm1 = fmaxf(m1, mx1);
        const float c0 = fexp(m0 - nm0);
        const float c1 = fexp(m1 - nm1);
        m0 = nm0; m1 = nm1;
        l0 *= c0;  l1 *= c1;
#pragma unroll
        for (int nd = 0; nd < 8; nd++) {
            oacc[nd][0] *= c0; oacc[nd][1] *= c0;
            oacc[nd][2] *= c1; oacc[nd][3] *= c1;
        }
#pragma unroll
        for (int nt = 0; nt < 8; nt++) {
            const float p0 = fexp(sacc[nt][0] - m0);
            const float p1 = fexp(sacc[nt][1] - m0);
            const float p2 = fexp(sacc[nt][2] - m1);
            const float p3 = fexp(sacc[nt][3] - m1);
            l0 += p0 + p1;
            l1 += p2 + p3;
            sacc[nt][0] = p0; sacc[nt][1] = p1;
            sacc[nt][2] = p2; sacc[nt][3] = p3;
        }

        // ---- O += P @ V  (fp16) ----
#pragma unroll
        for (int kc = 0; kc < 4; kc++) {
            uint32_t a[4];
            a[0] = packh2(sacc[2 * kc][0],     sacc[2 * kc][1]);
            a[1] = packh2(sacc[2 * kc][2],     sacc[2 * kc][3]);
            a[2] = packh2(sacc[2 * kc + 1][0], sacc[2 * kc + 1][1]);
            a[3] = packh2(sacc[2 * kc + 1][2], sacc[2 * kc + 1][3]);

            const int row = kc * 16 + ((vq & 1) << 3) + vt;
#pragma unroll
            for (int dn = 0; dn < 4; dn++) {
                const int seg = dn * 2 + (vq >> 1);
                uint32_t r4[4];
                LDSM_X4T(r4, vb + (uint32_t)(row * 128 + ((seg ^ (row & 7)) << 4)));
                MMA_F16(oacc[dn * 2],     a, r4);
                MMA_F16(oacc[dn * 2 + 1], a, (r4 + 2));
            }
        }
        __syncthreads();
    }

    // ---- epilogue: write ctx fp16 ----
    l0 += __shfl_xor_sync(0xffffffffu, l0, 1);
    l0 += __shfl_xor_sync(0xffffffffu, l0, 2);
    l1 += __shfl_xor_sync(0xffffffffu, l1, 1);
    l1 += __shfl_xor_sync(0xffffffffu, l1, 2);
    const float i0 = 1.0f / l0;
    const float i1 = 1.0f / l1;
    const int r0 = q0 + w * 16 + (lane >> 2);
#pragma unroll
    for (int nd = 0; nd < 8; nd++) {
        const int c = nd * 8 + (lane & 3) * 2;
        *(uint32_t*)(Oh + base + (size_t)r0 * D + c) =
            packh2(oacc[nd][0] * i0, oacc[nd][1] * i0);
        *(uint32_t*)(Oh + base + (size_t)(r0 + 8) * D + c) =
            packh2(oacc[nd][2] * i1, oacc[nd][3] * i1);
    }
}

// ---------------- residual + LayerNorm ----------------
__global__ void __launch_bounds__(256) ln_kernel(
    const float* __restrict__ x, const float* __restrict__ y,
    const float* __restrict__ gamma, const float* __restrict__ beta,
    float* __restrict__ out)
{
    __shared__ float red[8];
    const int row = blockIdx.x;
    const int tid = threadIdx.x;

    float4 xv = ((const float4*)(x + (size_t)row * D))[tid];
    float4 yv = ((const float4*)(y + (size_t)row * D))[tid];
    float v[4] = {xv.x + yv.x, xv.y + yv.y, xv.z + yv.z, xv.w + yv.w};

    float s = v[0] + v[1] + v[2] + v[3];
#pragma unroll
    for (int off = 16; off; off >>= 1) s += __shfl_xor_sync(0xffffffffu, s, off);
    if ((tid & 31) == 0) red[tid >> 5] = s;
    __syncthreads();
    if (tid == 0) {
        float t = 0.0f;
        for (int i = 0; i < 8; i++) t += red[i];
        red[0] = t;
    }
    __syncthreads();
    const float mean = red[0] * (1.0f / 1024.0f);
    __syncthreads();

    float ss = 0.0f;
#pragma unroll
    for (int i = 0; i < 4; i++) {
        float d = v[i] - mean;
        ss += d * d;
    }
#pragma unroll
    for (int off = 16; off; off >>= 1) ss += __shfl_xor_sync(0xffffffffu, ss, off);
    if ((tid & 31) == 0) red[tid >> 5] = ss;
    __syncthreads();
    if (tid == 0) {
        float t = 0.0f;
        for (int i = 0; i < 8; i++) t += red[i];
        red[0] = t;
    }
    __syncthreads();
    const float rstd = rsqrtf(red[0] * (1.0f / 1024.0f) + 1e-6f);

    float4 gv = ((const float4*)gamma)[tid];
    float4 bv = ((const float4*)beta)[tid];
    float4 ov;
    ov.x = (v[0] - mean) * rstd * gv.x + bv.x;
    ov.y = (v[1] - mean) * rstd * gv.y + bv.y;
    ov.z = (v[2] - mean) * rstd * gv.z + bv.z;
    ov.w = (v[3] - mean) * rstd * gv.w + bv.w;
    ((float4*)(out + (size_t)row * D))[tid] = ov;
}

// ---------------- launch ----------------
extern "C" void kernel_launch(void* const* d_in, const int* in_sizes, int n_in,
                              void* d_out, int out_size)
{
    const float* x     = (const float*)d_in[0];
    const float* Wq    = (const float*)d_in[1];
    const float* bq    = (const float*)d_in[2];
    const float* Wk    = (const float*)d_in[3];
    const float* bk    = (const float*)d_in[4];
    const float* Wv    = (const float*)d_in[5];
    const float* bv    = (const float*)d_in[6];
    const float* Wo    = (const float*)d_in[7];
    const float* bo    = (const float*)d_in[8];
    const float* gamma = (const float*)d_in[9];
    const float* beta  = (const float*)d_in[10];
    float* out = (float*)d_out;

    __half *xh, *wqh, *wkh, *wvh, *woh, *qh, *kh, *vh, *ch;
    float *att;
    cudaGetSymbolAddress((void**)&xh,  g_xh);
    cudaGetSymbolAddress((void**)&wqh, g_wqh);
    cudaGetSymbolAddress((void**)&wkh, g_wkh);
    cudaGetSymbolAddress((void**)&wvh, g_wvh);
    cudaGetSymbolAddress((void**)&woh, g_woh);
    cudaGetSymbolAddress((void**)&qh,  g_qh);
    cudaGetSymbolAddress((void**)&kh,  g_kh);
    cudaGetSymbolAddress((void**)&vh,  g_vh);
    cudaGetSymbolAddress((void**)&ch,  g_ch);
    cudaGetSymbolAddress((void**)&att, g_att);

    cudaFuncSetAttribute(gemm_mma, cudaFuncAttributeMaxDynamicSharedMemorySize, GEMM_SMEM);
    cudaFuncSetAttribute(attn_mma, cudaFuncAttributeMaxDynamicSharedMemorySize, ATTN_SMEM);

    to_half<<<TOK * D / 1024, 256>>>(x, xh, TOK * D);
    to_half<<<D * D / 1024, 256>>>(Wq, wqh, D * D);
    to_half<<<D * D / 1024, 256>>>(Wk, wkh, D * D);
    to_half<<<D * D / 1024, 256>>>(Wv, wvh, D * D);
    to_half<<<D * D / 1024, 256>>>(Wo, woh, D * D);

    GArgs qkv;
    qkv.A = xh;
    qkv.W[0] = wqh; qkv.W[1] = wkh; qkv.W[2] = wvh;
    qkv.b[0] = bq;  qkv.b[1] = bk;  qkv.b[2] = bv;
    qkv.Cf[0] = nullptr; qkv.Cf[1] = nullptr; qkv.Cf[2] = nullptr;
    qkv.Ch[0] = qh; qkv.Ch[1] = kh; qkv.Ch[2] = vh;
    gemm_mma<<<dim3(8, 32, 3), 256, GEMM_SMEM>>>(qkv);

    attn_mma<<<dim3(SEQ / 128, H, BAT), 256, ATTN_SMEM>>>(qh, kh, vh, ch);

    GArgs oproj;
    oproj.A = ch;
    oproj.W[0] = woh; oproj.W[1] = woh; oproj.W[2] = woh;
    oproj.b[0] = bo;  oproj.b[1] = bo;  oproj.b[2] = bo;
    oproj.Cf[0] = att; oproj.Cf[1] = att; oproj.Cf[2] = att;
    oproj.Ch[0] = nullptr; oproj.Ch[1] = nullptr; oproj.Ch[2] = nullptr;
    gemm_mma<<<dim3(8, 32, 1), 256, GEMM_SMEM>>>(oproj);

    ln_kernel<<<4096, 256>>>(x, att, gamma, beta, out);
}